// round 1
// baseline (speedup 1.0000x reference)
#include <cuda_runtime.h>
#include <math.h>

#define D_MODEL 1024
#define N_HEAD  16
#define D_K     64
#define BATCH   2
#define SEQ     2048
#define MROWS   (BATCH * SEQ)   // 4096

// ---------------- scratch (allocation-free: device globals) ----------------
__device__ float g_Qp[MROWS * D_MODEL];
__device__ float g_Kp[MROWS * D_MODEL];
__device__ float g_Vp[MROWS * D_MODEL];
__device__ float g_attn[MROWS * D_MODEL];

// ---------------- SGEMM: C[M,N] = A[M,K] @ W[K,N] + bias[N] ----------------
// 128x128 tile, BK=8, 256 threads, 8x8 per thread.
__global__ __launch_bounds__(256) void sgemm_bias(
    const float* __restrict__ A, const float* __restrict__ W,
    const float* __restrict__ bias, float* __restrict__ C,
    int M, int N, int K)
{
    const int BM = 128, BN = 128, BK = 8;
    __shared__ float As[BK][BM];   // transposed A tile
    __shared__ float Bs[BK][BN];

    const int tid = threadIdx.x;
    const int tx = tid % 16;       // 16 col-groups of 8
    const int ty = tid / 16;       // 16 row-groups of 8

    float acc[8][8] = {};

    // A-tile loader: 128x8 floats = 256 float4 (each thread 1)
    const int aRow = tid >> 1;            // 0..127
    const int aCol = (tid & 1) * 4;       // 0 or 4
    // W-tile loader: 8x128 floats = 256 float4
    const int wRow = tid >> 5;            // 0..7
    const int wCol = (tid & 31) * 4;      // 0..124

    const float* Aptr = A + (size_t)(blockIdx.y * BM) * K;
    const float* Wptr = W + blockIdx.x * BN;

    for (int k0 = 0; k0 < K; k0 += BK) {
        float4 a4 = *(const float4*)(Aptr + (size_t)aRow * K + k0 + aCol);
        As[aCol + 0][aRow] = a4.x;
        As[aCol + 1][aRow] = a4.y;
        As[aCol + 2][aRow] = a4.z;
        As[aCol + 3][aRow] = a4.w;
        float4 w4 = *(const float4*)(Wptr + (size_t)(k0 + wRow) * N + wCol);
        *(float4*)&Bs[wRow][wCol] = w4;
        __syncthreads();

        #pragma unroll
        for (int kk = 0; kk < BK; kk++) {
            float4 a0 = *(const float4*)&As[kk][ty * 8];
            float4 a1 = *(const float4*)&As[kk][ty * 8 + 4];
            float4 b0 = *(const float4*)&Bs[kk][tx * 8];
            float4 b1 = *(const float4*)&Bs[kk][tx * 8 + 4];
            float af[8] = {a0.x, a0.y, a0.z, a0.w, a1.x, a1.y, a1.z, a1.w};
            float bf[8] = {b0.x, b0.y, b0.z, b0.w, b1.x, b1.y, b1.z, b1.w};
            #pragma unroll
            for (int i = 0; i < 8; i++)
                #pragma unroll
                for (int j = 0; j < 8; j++)
                    acc[i][j] += af[i] * bf[j];
        }
        __syncthreads();
    }

    // epilogue: +bias, store
    #pragma unroll
    for (int i = 0; i < 8; i++) {
        const size_t r = (size_t)blockIdx.y * BM + ty * 8 + i;
        #pragma unroll
        for (int j = 0; j < 8; j += 4) {
            const int c = blockIdx.x * BN + tx * 8 + j;
            float4 o;
            o.x = acc[i][j + 0] + bias[c + 0];
            o.y = acc[i][j + 1] + bias[c + 1];
            o.z = acc[i][j + 2] + bias[c + 2];
            o.w = acc[i][j + 3] + bias[c + 3];
            *(float4*)(C + r * N + c) = o;
        }
    }
}

// ---------------- Flash attention (fp32, online softmax) ----------------
// Grid: (SEQ/64 query tiles, H*B head-batches). 256 threads.
// Thread (ty,tx): ty=tid/16 owns 4 query rows, tx=tid%16 owns 4 cols
// (score cols during QK^T, output dims during PV).
// Dynamic smem: Qs, Ks, Vs, Ss each 64 x 65 floats (padded).
#define ATT_LDS 65
#define ATT_SMEM_BYTES (4 * 64 * ATT_LDS * sizeof(float))

__global__ __launch_bounds__(256) void attn_kernel()
{
    extern __shared__ float smem[];
    float* Qs = smem;
    float* Ks = smem + 64 * ATT_LDS;
    float* Vs = smem + 2 * 64 * ATT_LDS;
    float* Ss = smem + 3 * 64 * ATT_LDS;

    const int qt = blockIdx.x;          // query tile
    const int hb = blockIdx.y;          // h*B + b  (split_heads order)
    const int h = hb / BATCH;
    const int b = hb % BATCH;
    const int tid = threadIdx.x;
    const int tx = tid % 16;
    const int ty = tid / 16;
    const float scale = 0.125f;         // 1/sqrt(64)

    const float* Qbase = g_Qp + (size_t)b * SEQ * D_MODEL + h * D_K;
    const float* Kbase = g_Kp + (size_t)b * SEQ * D_MODEL + h * D_K;
    const float* Vbase = g_Vp + (size_t)b * SEQ * D_MODEL + h * D_K;

    // load Q tile (64 rows x 64 dims)
    for (int i = tid; i < 64 * 64; i += 256) {
        int r = i >> 6, d = i & 63;
        Qs[r * ATT_LDS + d] = Qbase[(size_t)(qt * 64 + r) * D_MODEL + d];
    }

    float m_i[4], l_i[4];
    float acc[4][4] = {};
    #pragma unroll
    for (int i = 0; i < 4; i++) { m_i[i] = -1e30f; l_i[i] = 0.0f; }

    for (int kt = 0; kt < SEQ / 64; kt++) {
        __syncthreads();   // prior-iter consumers done before overwrite
        for (int i = tid; i < 64 * 64; i += 256) {
            int r = i >> 6, d = i & 63;
            Ks[r * ATT_LDS + d] = Kbase[(size_t)(kt * 64 + r) * D_MODEL + d];
            Vs[r * ATT_LDS + d] = Vbase[(size_t)(kt * 64 + r) * D_MODEL + d];
        }
        __syncthreads();

        // S = scale * Q K^T  (per-thread 4x4)
        float s[4][4] = {};
        #pragma unroll
        for (int d = 0; d < 64; d++) {
            float qf[4], kf[4];
            #pragma unroll
            for (int i = 0; i < 4; i++) qf[i] = Qs[(ty * 4 + i) * ATT_LDS + d];
            #pragma unroll
            for (int j = 0; j < 4; j++) kf[j] = Ks[(tx * 4 + j) * ATT_LDS + d];
            #pragma unroll
            for (int i = 0; i < 4; i++)
                #pragma unroll
                for (int j = 0; j < 4; j++)
                    s[i][j] += qf[i] * kf[j];
        }

        // online softmax per owned query row (replicated across 16-lane group)
        #pragma unroll
        for (int i = 0; i < 4; i++) {
            float mx = -1e30f;
            #pragma unroll
            for (int j = 0; j < 4; j++) {
                s[i][j] *= scale;
                mx = fmaxf(mx, s[i][j]);
            }
            #pragma unroll
            for (int off = 1; off < 16; off <<= 1)
                mx = fmaxf(mx, __shfl_xor_sync(0xffffffffu, mx, off, 16));
            float m_new = fmaxf(m_i[i], mx);
            float alpha = __expf(m_i[i] - m_new);
            float rs = 0.0f;
            #pragma unroll
            for (int j = 0; j < 4; j++) {
                float p = __expf(s[i][j] - m_new);
                s[i][j] = p;
                rs += p;
            }
            #pragma unroll
            for (int off = 1; off < 16; off <<= 1)
                rs += __shfl_xor_sync(0xffffffffu, rs, off, 16);
            l_i[i] = l_i[i] * alpha + rs;
            m_i[i] = m_new;
            #pragma unroll
            for (int j = 0; j < 4; j++) acc[i][j] *= alpha;
            // stage P into smem for the PV product
            #pragma unroll
            for (int j = 0; j < 4; j++)
                Ss[(ty * 4 + i) * ATT_LDS + tx * 4 + j] = s[i][j];
        }
        __syncthreads();

        // acc += P @ V  (thread: rows ty*4.., dims tx*4..)
        #pragma unroll
        for (int k = 0; k < 64; k++) {
            float pf[4], vf[4];
            #pragma unroll
            for (int i = 0; i < 4; i++) pf[i] = Ss[(ty * 4 + i) * ATT_LDS + k];
            #pragma unroll
            for (int j = 0; j < 4; j++) vf[j] = Vs[k * ATT_LDS + tx * 4 + j];
            #pragma unroll
            for (int i = 0; i < 4; i++)
                #pragma unroll
                for (int j = 0; j < 4; j++)
                    acc[i][j] += pf[i] * vf[j];
        }
    }

    // normalize + write into merged [B,S,D] layout (head h -> cols h*64..)
    #pragma unroll
    for (int i = 0; i < 4; i++) {
        const float inv_l = 1.0f / l_i[i];
        const size_t row = (size_t)b * SEQ + qt * 64 + ty * 4 + i;
        #pragma unroll
        for (int j = 0; j < 4; j++)
            g_attn[row * D_MODEL + h * D_K + tx * 4 + j] = acc[i][j] * inv_l;
    }
}

// ---------------- launch ----------------
extern "C" void kernel_launch(void* const* d_in, const int* in_sizes, int n_in,
                              void* d_out, int out_size)
{
    const float* q   = (const float*)d_in[0];
    const float* k   = (const float*)d_in[1];
    const float* v   = (const float*)d_in[2];
    const float* w_q = (const float*)d_in[3];
    const float* b_q = (const float*)d_in[4];
    const float* w_k = (const float*)d_in[5];
    const float* b_k = (const float*)d_in[6];
    const float* w_v = (const float*)d_in[7];
    const float* b_v = (const float*)d_in[8];
    const float* w_o = (const float*)d_in[9];
    const float* b_o = (const float*)d_in[10];
    float* out = (float*)d_out;

    float *Qp, *Kp, *Vp, *attn;
    cudaGetSymbolAddress((void**)&Qp,   g_Qp);
    cudaGetSymbolAddress((void**)&Kp,   g_Kp);
    cudaGetSymbolAddress((void**)&Vp,   g_Vp);
    cudaGetSymbolAddress((void**)&attn, g_attn);

    cudaFuncSetAttribute(attn_kernel,
                         cudaFuncAttributeMaxDynamicSharedMemorySize,
                         (int)ATT_SMEM_BYTES);

    dim3 gemmGrid(D_MODEL / 128, MROWS / 128);   // (8, 32)
    sgemm_bias<<<gemmGrid, 256>>>(q, w_q, b_q, Qp, MROWS, D_MODEL, D_MODEL);
    sgemm_bias<<<gemmGrid, 256>>>(k, w_k, b_k, Kp, MROWS, D_MODEL, D_MODEL);
    sgemm_bias<<<gemmGrid, 256>>>(v, w_v, b_v, Vp, MROWS, D_MODEL, D_MODEL);

    dim3 attnGrid(SEQ / 64, N_HEAD * BATCH);     // (32, 32)
    attn_kernel<<<attnGrid, 256, ATT_SMEM_BYTES>>>();

    sgemm_bias<<<gemmGrid, 256>>>(attn, w_o, b_o, out, MROWS, D_MODEL, D_MODEL);
}

// round 3
// speedup vs baseline: 1.2781x; 1.2781x over previous
#include <cuda_runtime.h>
#include <cuda_bf16.h>
#include <cstdint>
#include <math.h>

#define D_MODEL 1024
#define N_HEAD  16
#define D_K     64
#define BATCH   2
#define SEQ     2048
#define MROWS   (BATCH * SEQ)   // 4096

// ===================== scratch (allocation-free: device globals) ============
__device__ float g_Qp[MROWS * D_MODEL];
__device__ float g_Kp[MROWS * D_MODEL];
__device__ float g_Vp[MROWS * D_MODEL];
__device__ float g_attn[MROWS * D_MODEL];
__device__ __nv_bfloat16 g_Ahi[MROWS * D_MODEL];
__device__ __nv_bfloat16 g_Alo[MROWS * D_MODEL];
__device__ __nv_bfloat16 g_WhiT[D_MODEL * D_MODEL];
__device__ __nv_bfloat16 g_WloT[D_MODEL * D_MODEL];

// ===================== warp-mma helpers (baseline sm_100 features) ==========
__device__ __forceinline__ uint32_t smem_u32_of(const void* p) {
    uint32_t a;
    asm("{ .reg .u64 t; cvta.to.shared.u64 t, %1; cvt.u32.u64 %0, t; }"
        : "=r"(a) : "l"(p));
    return a;
}

__device__ __forceinline__ void ldmx4(uint32_t addr, uint32_t& r0, uint32_t& r1,
                                      uint32_t& r2, uint32_t& r3) {
    asm volatile("ldmatrix.sync.aligned.m8n8.x4.shared.b16 {%0,%1,%2,%3}, [%4];"
                 : "=r"(r0), "=r"(r1), "=r"(r2), "=r"(r3) : "r"(addr));
}

__device__ __forceinline__ void mma16816(float* c, const uint32_t* a,
                                         uint32_t b0, uint32_t b1) {
    asm volatile(
        "mma.sync.aligned.m16n8k16.row.col.f32.bf16.bf16.f32 "
        "{%0,%1,%2,%3}, {%4,%5,%6,%7}, {%8,%9}, {%0,%1,%2,%3};"
        : "+f"(c[0]), "+f"(c[1]), "+f"(c[2]), "+f"(c[3])
        : "r"(a[0]), "r"(a[1]), "r"(a[2]), "r"(a[3]), "r"(b0), "r"(b1));
}

// ===================== split / transpose-split conversion ===================
__global__ __launch_bounds__(256) void split_kernel(
    const float* __restrict__ x, __nv_bfloat16* __restrict__ hi,
    __nv_bfloat16* __restrict__ lo, int n4)
{
    int i = blockIdx.x * blockDim.x + threadIdx.x;
    if (i >= n4) return;
    float4 v = ((const float4*)x)[i];
    __nv_bfloat16 h0 = __float2bfloat16_rn(v.x);
    __nv_bfloat16 h1 = __float2bfloat16_rn(v.y);
    __nv_bfloat16 h2 = __float2bfloat16_rn(v.z);
    __nv_bfloat16 h3 = __float2bfloat16_rn(v.w);
    __nv_bfloat16 l0 = __float2bfloat16_rn(v.x - __bfloat162float(h0));
    __nv_bfloat16 l1 = __float2bfloat16_rn(v.y - __bfloat162float(h1));
    __nv_bfloat16 l2 = __float2bfloat16_rn(v.z - __bfloat162float(h2));
    __nv_bfloat16 l3 = __float2bfloat16_rn(v.w - __bfloat162float(h3));
    ((__nv_bfloat162*)hi)[i * 2 + 0] = __nv_bfloat162(h0, h1);
    ((__nv_bfloat162*)hi)[i * 2 + 1] = __nv_bfloat162(h2, h3);
    ((__nv_bfloat162*)lo)[i * 2 + 0] = __nv_bfloat162(l0, l1);
    ((__nv_bfloat162*)lo)[i * 2 + 1] = __nv_bfloat162(l2, l3);
}

// W[K][N] fp32 -> WhiT/WloT [N][K] bf16 (transpose + split)
__global__ __launch_bounds__(256) void wsplit_kernel(
    const float* __restrict__ W, __nv_bfloat16* __restrict__ hiT,
    __nv_bfloat16* __restrict__ loT)
{
    __shared__ float t[32][33];
    const int nBase = blockIdx.x * 32, kBase = blockIdx.y * 32;
    const int tx = threadIdx.x, ty = threadIdx.y;   // 32 x 8
    #pragma unroll
    for (int r = 0; r < 4; r++)
        t[ty + 8 * r][tx] = W[(size_t)(kBase + ty + 8 * r) * D_MODEL + nBase + tx];
    __syncthreads();
    #pragma unroll
    for (int r = 0; r < 4; r++) {
        float v = t[tx][ty + 8 * r];
        __nv_bfloat16 h = __float2bfloat16_rn(v);
        __nv_bfloat16 l = __float2bfloat16_rn(v - __bfloat162float(h));
        size_t o = (size_t)(nBase + ty + 8 * r) * D_MODEL + kBase + tx;
        hiT[o] = h;
        loT[o] = l;
    }
}

// ===================== HMMA split-bf16 GEMM =================================
// C[4096,1024] = A @ W + bias.  A as (Ahi,Alo)[M,K] bf16, W as (WhiT,WloT)[N,K].
// CTA tile 128x128, BK=32, 8 warps (warp tile 64x32), m16n8k16 mma, 3 products.
#define GBM 128
#define GBN 128
#define GBK 32
#define SPAD 40   // bf16 row stride (32 data + 8 pad) -> conflict-free ldmatrix

__global__ __launch_bounds__(256, 2) void gemm_tc(
    const __nv_bfloat16* __restrict__ Ahi, const __nv_bfloat16* __restrict__ Alo,
    const __nv_bfloat16* __restrict__ BhiT, const __nv_bfloat16* __restrict__ BloT,
    const float* __restrict__ bias, float* __restrict__ C)
{
    __shared__ __nv_bfloat16 sAhi[GBM][SPAD];
    __shared__ __nv_bfloat16 sAlo[GBM][SPAD];
    __shared__ __nv_bfloat16 sBhi[GBN][SPAD];
    __shared__ __nv_bfloat16 sBlo[GBN][SPAD];

    const int tid = threadIdx.x;
    const int wid = tid >> 5;
    const int lane = tid & 31;
    const int warp_m = wid & 1;          // 2 warps over M (64 rows each)
    const int warp_n = wid >> 1;         // 4 warps over N (32 cols each)

    const size_t rBase = (size_t)blockIdx.y * GBM;
    const size_t nBase = (size_t)blockIdx.x * GBN;

    float acc[4][4][4] = {};             // [mi][ni][frag]

    // ldmatrix base addresses (per-lane)
    const int lrow = lane & 15;          // 0..15
    const int lcol8 = (lane >> 4) * 8;   // 0 or 8
    const uint32_t aHiBase = smem_u32_of(&sAhi[warp_m * 64 + lrow][lcol8]);
    const uint32_t aLoBase = smem_u32_of(&sAlo[warp_m * 64 + lrow][lcol8]);
    const uint32_t bHiBase = smem_u32_of(&sBhi[warp_n * 32 + lrow][lcol8]);
    const uint32_t bLoBase = smem_u32_of(&sBlo[warp_n * 32 + lrow][lcol8]);

    for (int k0 = 0; k0 < D_MODEL; k0 += GBK) {
        // ---- load 4 tiles: 128 rows x 32 bf16 each = 512 uint4 per tile ----
        #pragma unroll
        for (int it = 0; it < 2; it++) {
            const int u = tid + it * 256;        // 0..511
            const int r = u >> 2, c4 = u & 3;    // row, 16B-chunk
            const size_t gA = (rBase + r) * D_MODEL + k0 + c4 * 8;
            const size_t gB = (nBase + r) * D_MODEL + k0 + c4 * 8;
            *(uint4*)&sAhi[r][c4 * 8] = *(const uint4*)(Ahi + gA);
            *(uint4*)&sAlo[r][c4 * 8] = *(const uint4*)(Alo + gA);
            *(uint4*)&sBhi[r][c4 * 8] = *(const uint4*)(BhiT + gB);
            *(uint4*)&sBlo[r][c4 * 8] = *(const uint4*)(BloT + gB);
        }
        __syncthreads();

        #pragma unroll
        for (int kk = 0; kk < GBK; kk += 16) {
            const uint32_t koff = kk * 2;        // bytes
            // B fragments: 2 x ldmatrix.x4 covers 4 n-tiles (hi and lo)
            uint32_t bh[8], bl[8];
            #pragma unroll
            for (int p = 0; p < 2; p++) {
                uint32_t r0, r1, r2, r3;
                ldmx4(bHiBase + p * 16 * SPAD * 2 + koff, r0, r1, r2, r3);
                bh[p * 4 + 0] = r0; bh[p * 4 + 1] = r2;   // n-tile 2p
                bh[p * 4 + 2] = r1; bh[p * 4 + 3] = r3;   // n-tile 2p+1
                ldmx4(bLoBase + p * 16 * SPAD * 2 + koff, r0, r1, r2, r3);
                bl[p * 4 + 0] = r0; bl[p * 4 + 1] = r2;
                bl[p * 4 + 2] = r1; bl[p * 4 + 3] = r3;
            }
            #pragma unroll
            for (int mi = 0; mi < 4; mi++) {
                uint32_t ah[4], al[4];
                ldmx4(aHiBase + mi * 16 * SPAD * 2 + koff, ah[0], ah[1], ah[2], ah[3]);
                ldmx4(aLoBase + mi * 16 * SPAD * 2 + koff, al[0], al[1], al[2], al[3]);
                #pragma unroll
                for (int ni = 0; ni < 4; ni++) {
                    const uint32_t b0h = bh[(ni >> 1) * 4 + (ni & 1) * 2];
                    const uint32_t b1h = bh[(ni >> 1) * 4 + (ni & 1) * 2 + 1];
                    const uint32_t b0l = bl[(ni >> 1) * 4 + (ni & 1) * 2];
                    const uint32_t b1l = bl[(ni >> 1) * 4 + (ni & 1) * 2 + 1];
                    mma16816(acc[mi][ni], ah, b0h, b1h);
                    mma16816(acc[mi][ni], ah, b0l, b1l);
                    mma16816(acc[mi][ni], al, b0h, b1h);
                }
            }
        }
        __syncthreads();
    }

    // ---- epilogue: +bias, float2 stores ----
    const int crow = lane >> 2;          // 0..7
    const int ccol = (lane & 3) * 2;     // 0,2,4,6
    #pragma unroll
    for (int mi = 0; mi < 4; mi++) {
        #pragma unroll
        for (int ni = 0; ni < 4; ni++) {
            const size_t row0 = rBase + warp_m * 64 + mi * 16 + crow;
            const size_t col = nBase + warp_n * 32 + ni * 8 + ccol;
            const float b0 = bias[col], b1 = bias[col + 1];
            float2 o0 = {acc[mi][ni][0] + b0, acc[mi][ni][1] + b1};
            float2 o1 = {acc[mi][ni][2] + b0, acc[mi][ni][3] + b1};
            *(float2*)(C + row0 * D_MODEL + col) = o0;
            *(float2*)(C + (row0 + 8) * D_MODEL + col) = o1;
        }
    }
}

// ===================== Flash attention (fp32, unchanged from R1) ============
#define ATT_LDS 65
#define ATT_SMEM_BYTES (4 * 64 * ATT_LDS * sizeof(float))

__global__ __launch_bounds__(256) void attn_kernel()
{
    extern __shared__ float smemf[];
    float* Qs = smemf;
    float* Ks = smemf + 64 * ATT_LDS;
    float* Vs = smemf + 2 * 64 * ATT_LDS;
    float* Ss = smemf + 3 * 64 * ATT_LDS;

    const int qt = blockIdx.x;
    const int hb = blockIdx.y;
    const int h = hb / BATCH;
    const int b = hb % BATCH;
    const int tid = threadIdx.x;
    const int tx = tid % 16;
    const int ty = tid / 16;
    const float scale = 0.125f;

    const float* Qbase = g_Qp + (size_t)b * SEQ * D_MODEL + h * D_K;
    const float* Kbase = g_Kp + (size_t)b * SEQ * D_MODEL + h * D_K;
    const float* Vbase = g_Vp + (size_t)b * SEQ * D_MODEL + h * D_K;

    for (int i = tid; i < 64 * 64; i += 256) {
        int r = i >> 6, d = i & 63;
        Qs[r * ATT_LDS + d] = Qbase[(size_t)(qt * 64 + r) * D_MODEL + d];
    }

    float m_i[4], l_i[4];
    float acc[4][4] = {};
    #pragma unroll
    for (int i = 0; i < 4; i++) { m_i[i] = -1e30f; l_i[i] = 0.0f; }

    for (int kt = 0; kt < SEQ / 64; kt++) {
        __syncthreads();
        for (int i = tid; i < 64 * 64; i += 256) {
            int r = i >> 6, d = i & 63;
            Ks[r * ATT_LDS + d] = Kbase[(size_t)(kt * 64 + r) * D_MODEL + d];
            Vs[r * ATT_LDS + d] = Vbase[(size_t)(kt * 64 + r) * D_MODEL + d];
        }
        __syncthreads();

        float s[4][4] = {};
        #pragma unroll
        for (int d = 0; d < 64; d++) {
            float qf[4], kf[4];
            #pragma unroll
            for (int i = 0; i < 4; i++) qf[i] = Qs[(ty * 4 + i) * ATT_LDS + d];
            #pragma unroll
            for (int j = 0; j < 4; j++) kf[j] = Ks[(tx * 4 + j) * ATT_LDS + d];
            #pragma unroll
            for (int i = 0; i < 4; i++)
                #pragma unroll
                for (int j = 0; j < 4; j++)
                    s[i][j] += qf[i] * kf[j];
        }

        #pragma unroll
        for (int i = 0; i < 4; i++) {
            float mx = -1e30f;
            #pragma unroll
            for (int j = 0; j < 4; j++) {
                s[i][j] *= scale;
                mx = fmaxf(mx, s[i][j]);
            }
            #pragma unroll
            for (int off = 1; off < 16; off <<= 1)
                mx = fmaxf(mx, __shfl_xor_sync(0xffffffffu, mx, off, 16));
            float m_new = fmaxf(m_i[i], mx);
            float alpha = __expf(m_i[i] - m_new);
            float rs = 0.0f;
            #pragma unroll
            for (int j = 0; j < 4; j++) {
                float p = __expf(s[i][j] - m_new);
                s[i][j] = p;
                rs += p;
            }
            #pragma unroll
            for (int off = 1; off < 16; off <<= 1)
                rs += __shfl_xor_sync(0xffffffffu, rs, off, 16);
            l_i[i] = l_i[i] * alpha + rs;
            m_i[i] = m_new;
            #pragma unroll
            for (int j = 0; j < 4; j++) acc[i][j] *= alpha;
            #pragma unroll
            for (int j = 0; j < 4; j++)
                Ss[(ty * 4 + i) * ATT_LDS + tx * 4 + j] = s[i][j];
        }
        __syncthreads();

        #pragma unroll
        for (int k = 0; k < 64; k++) {
            float pf[4], vf[4];
            #pragma unroll
            for (int i = 0; i < 4; i++) pf[i] = Ss[(ty * 4 + i) * ATT_LDS + k];
            #pragma unroll
            for (int j = 0; j < 4; j++) vf[j] = Vs[k * ATT_LDS + tx * 4 + j];
            #pragma unroll
            for (int i = 0; i < 4; i++)
                #pragma unroll
                for (int j = 0; j < 4; j++)
                    acc[i][j] += pf[i] * vf[j];
        }
    }

    #pragma unroll
    for (int i = 0; i < 4; i++) {
        const float inv_l = 1.0f / l_i[i];
        const size_t row = (size_t)b * SEQ + qt * 64 + ty * 4 + i;
        #pragma unroll
        for (int j = 0; j < 4; j++)
            g_attn[row * D_MODEL + h * D_K + tx * 4 + j] = acc[i][j] * inv_l;
    }
}

// ===================== launch ==============================================
extern "C" void kernel_launch(void* const* d_in, const int* in_sizes, int n_in,
                              void* d_out, int out_size)
{
    const float* q   = (const float*)d_in[0];
    const float* k   = (const float*)d_in[1];
    const float* v   = (const float*)d_in[2];
    const float* w_q = (const float*)d_in[3];
    const float* b_q = (const float*)d_in[4];
    const float* w_k = (const float*)d_in[5];
    const float* b_k = (const float*)d_in[6];
    const float* w_v = (const float*)d_in[7];
    const float* b_v = (const float*)d_in[8];
    const float* w_o = (const float*)d_in[9];
    const float* b_o = (const float*)d_in[10];
    float* out = (float*)d_out;

    float *Qp, *Kp, *Vp, *attn;
    __nv_bfloat16 *Ahi, *Alo, *Whi, *Wlo;
    cudaGetSymbolAddress((void**)&Qp,   g_Qp);
    cudaGetSymbolAddress((void**)&Kp,   g_Kp);
    cudaGetSymbolAddress((void**)&Vp,   g_Vp);
    cudaGetSymbolAddress((void**)&attn, g_attn);
    cudaGetSymbolAddress((void**)&Ahi,  g_Ahi);
    cudaGetSymbolAddress((void**)&Alo,  g_Alo);
    cudaGetSymbolAddress((void**)&Whi,  g_WhiT);
    cudaGetSymbolAddress((void**)&Wlo,  g_WloT);

    cudaFuncSetAttribute(attn_kernel, cudaFuncAttributeMaxDynamicSharedMemorySize,
                         (int)ATT_SMEM_BYTES);

    const dim3 wgrid(D_MODEL / 32, D_MODEL / 32), wblk(32, 8);
    const int n4 = MROWS * D_MODEL / 4;
    const int splitBlocks = n4 / 256;
    const dim3 ggrid(D_MODEL / GBN, MROWS / GBM);   // (8, 32)

    // Q projection
    wsplit_kernel<<<wgrid, wblk>>>(w_q, Whi, Wlo);
    split_kernel<<<splitBlocks, 256>>>(q, Ahi, Alo, n4);
    gemm_tc<<<ggrid, 256>>>(Ahi, Alo, Whi, Wlo, b_q, Qp);
    // K projection
    wsplit_kernel<<<wgrid, wblk>>>(w_k, Whi, Wlo);
    split_kernel<<<splitBlocks, 256>>>(k, Ahi, Alo, n4);
    gemm_tc<<<ggrid, 256>>>(Ahi, Alo, Whi, Wlo, b_k, Kp);
    // V projection
    wsplit_kernel<<<wgrid, wblk>>>(w_v, Whi, Wlo);
    split_kernel<<<splitBlocks, 256>>>(v, Ahi, Alo, n4);
    gemm_tc<<<ggrid, 256>>>(Ahi, Alo, Whi, Wlo, b_v, Vp);

    // attention
    dim3 attnGrid(SEQ / 64, N_HEAD * BATCH);
    attn_kernel<<<attnGrid, 256, ATT_SMEM_BYTES>>>();

    // output projection
    wsplit_kernel<<<wgrid, wblk>>>(w_o, Whi, Wlo);
    split_kernel<<<splitBlocks, 256>>>(attn, Ahi, Alo, n4);
    gemm_tc<<<ggrid, 256>>>(Ahi, Alo, Whi, Wlo, b_o, out);
}

// round 4
// speedup vs baseline: 2.2453x; 1.7567x over previous
#include <cuda_runtime.h>
#include <cuda_bf16.h>
#include <cstdint>
#include <math.h>

#define D_MODEL 1024
#define N_HEAD  16
#define D_K     64
#define BATCH   2
#define SEQ     2048
#define MROWS   (BATCH * SEQ)   // 4096

// ===================== scratch (allocation-free: device globals) ============
__device__ __nv_bfloat16 g_Ahi[MROWS * D_MODEL];
__device__ __nv_bfloat16 g_Alo[MROWS * D_MODEL];
__device__ __nv_bfloat16 g_WhiT[D_MODEL * D_MODEL];
__device__ __nv_bfloat16 g_WloT[D_MODEL * D_MODEL];
__device__ __nv_bfloat16 g_Qhi[MROWS * D_MODEL];
__device__ __nv_bfloat16 g_Qlo[MROWS * D_MODEL];
__device__ __nv_bfloat16 g_Khi[MROWS * D_MODEL];
__device__ __nv_bfloat16 g_Klo[MROWS * D_MODEL];
__device__ __nv_bfloat16 g_Vhi[MROWS * D_MODEL];
__device__ __nv_bfloat16 g_Vlo[MROWS * D_MODEL];

// ===================== warp-mma helpers =====================================
__device__ __forceinline__ uint32_t smem_u32_of(const void* p) {
    uint32_t a;
    asm("{ .reg .u64 t; cvta.to.shared.u64 t, %1; cvt.u32.u64 %0, t; }"
        : "=r"(a) : "l"(p));
    return a;
}
__device__ __forceinline__ void ldmx4(uint32_t addr, uint32_t& r0, uint32_t& r1,
                                      uint32_t& r2, uint32_t& r3) {
    asm volatile("ldmatrix.sync.aligned.m8n8.x4.shared.b16 {%0,%1,%2,%3}, [%4];"
                 : "=r"(r0), "=r"(r1), "=r"(r2), "=r"(r3) : "r"(addr));
}
__device__ __forceinline__ void ldmx4t(uint32_t addr, uint32_t& r0, uint32_t& r1,
                                       uint32_t& r2, uint32_t& r3) {
    asm volatile("ldmatrix.sync.aligned.m8n8.x4.trans.shared.b16 {%0,%1,%2,%3}, [%4];"
                 : "=r"(r0), "=r"(r1), "=r"(r2), "=r"(r3) : "r"(addr));
}
__device__ __forceinline__ void mma16816(float* c, const uint32_t* a,
                                         uint32_t b0, uint32_t b1) {
    asm volatile(
        "mma.sync.aligned.m16n8k16.row.col.f32.bf16.bf16.f32 "
        "{%0,%1,%2,%3}, {%4,%5,%6,%7}, {%8,%9}, {%0,%1,%2,%3};"
        : "+f"(c[0]), "+f"(c[1]), "+f"(c[2]), "+f"(c[3])
        : "r"(a[0]), "r"(a[1]), "r"(a[2]), "r"(a[3]), "r"(b0), "r"(b1));
}
__device__ __forceinline__ uint32_t pack_bf16(float x, float y) {
    __nv_bfloat162 t = __floats2bfloat162_rn(x, y);
    return *(uint32_t*)&t;
}

// ===================== split / transpose-split conversion ===================
__global__ __launch_bounds__(256) void split_kernel(
    const float* __restrict__ x, __nv_bfloat16* __restrict__ hi,
    __nv_bfloat16* __restrict__ lo, int n4)
{
    int i = blockIdx.x * blockDim.x + threadIdx.x;
    if (i >= n4) return;
    float4 v = ((const float4*)x)[i];
    __nv_bfloat16 h0 = __float2bfloat16_rn(v.x);
    __nv_bfloat16 h1 = __float2bfloat16_rn(v.y);
    __nv_bfloat16 h2 = __float2bfloat16_rn(v.z);
    __nv_bfloat16 h3 = __float2bfloat16_rn(v.w);
    __nv_bfloat16 l0 = __float2bfloat16_rn(v.x - __bfloat162float(h0));
    __nv_bfloat16 l1 = __float2bfloat16_rn(v.y - __bfloat162float(h1));
    __nv_bfloat16 l2 = __float2bfloat16_rn(v.z - __bfloat162float(h2));
    __nv_bfloat16 l3 = __float2bfloat16_rn(v.w - __bfloat162float(h3));
    ((__nv_bfloat162*)hi)[i * 2 + 0] = __nv_bfloat162(h0, h1);
    ((__nv_bfloat162*)hi)[i * 2 + 1] = __nv_bfloat162(h2, h3);
    ((__nv_bfloat162*)lo)[i * 2 + 0] = __nv_bfloat162(l0, l1);
    ((__nv_bfloat162*)lo)[i * 2 + 1] = __nv_bfloat162(l2, l3);
}

// W[K][N] fp32 -> WhiT/WloT [N][K] bf16 (transpose + split)
__global__ __launch_bounds__(256) void wsplit_kernel(
    const float* __restrict__ W, __nv_bfloat16* __restrict__ hiT,
    __nv_bfloat16* __restrict__ loT)
{
    __shared__ float t[32][33];
    const int nBase = blockIdx.x * 32, kBase = blockIdx.y * 32;
    const int tx = threadIdx.x, ty = threadIdx.y;   // 32 x 8
    #pragma unroll
    for (int r = 0; r < 4; r++)
        t[ty + 8 * r][tx] = W[(size_t)(kBase + ty + 8 * r) * D_MODEL + nBase + tx];
    __syncthreads();
    #pragma unroll
    for (int r = 0; r < 4; r++) {
        float v = t[tx][ty + 8 * r];
        __nv_bfloat16 h = __float2bfloat16_rn(v);
        __nv_bfloat16 l = __float2bfloat16_rn(v - __bfloat162float(h));
        size_t o = (size_t)(nBase + ty + 8 * r) * D_MODEL + kBase + tx;
        hiT[o] = h;
        loT[o] = l;
    }
}

// ===================== HMMA split-bf16 GEMM =================================
// C = A @ W + bias, optionally emitting scaled split-bf16 (Chi/Clo) instead
// of fp32 C.  CTA 128x128, BK=32, 8 warps (64x32 each), m16n8k16 x 3 products.
#define GBM 128
#define GBN 128
#define GBK 32
#define SPAD 40

__global__ __launch_bounds__(256, 2) void gemm_tc(
    const __nv_bfloat16* __restrict__ Ahi, const __nv_bfloat16* __restrict__ Alo,
    const __nv_bfloat16* __restrict__ BhiT, const __nv_bfloat16* __restrict__ BloT,
    const float* __restrict__ bias, float* __restrict__ C,
    __nv_bfloat16* __restrict__ Chi, __nv_bfloat16* __restrict__ Clo, float scale)
{
    __shared__ __nv_bfloat16 sAhi[GBM][SPAD];
    __shared__ __nv_bfloat16 sAlo[GBM][SPAD];
    __shared__ __nv_bfloat16 sBhi[GBN][SPAD];
    __shared__ __nv_bfloat16 sBlo[GBN][SPAD];

    const int tid = threadIdx.x;
    const int wid = tid >> 5;
    const int lane = tid & 31;
    const int warp_m = wid & 1;
    const int warp_n = wid >> 1;

    const size_t rBase = (size_t)blockIdx.y * GBM;
    const size_t nBase = (size_t)blockIdx.x * GBN;

    float acc[4][4][4] = {};

    const int lrow = lane & 15;
    const int lcol8 = (lane >> 4) * 8;
    const uint32_t aHiBase = smem_u32_of(&sAhi[warp_m * 64 + lrow][lcol8]);
    const uint32_t aLoBase = smem_u32_of(&sAlo[warp_m * 64 + lrow][lcol8]);
    const uint32_t bHiBase = smem_u32_of(&sBhi[warp_n * 32 + lrow][lcol8]);
    const uint32_t bLoBase = smem_u32_of(&sBlo[warp_n * 32 + lrow][lcol8]);

    for (int k0 = 0; k0 < D_MODEL; k0 += GBK) {
        #pragma unroll
        for (int it = 0; it < 2; it++) {
            const int u = tid + it * 256;
            const int r = u >> 2, c4 = u & 3;
            const size_t gA = (rBase + r) * D_MODEL + k0 + c4 * 8;
            const size_t gB = (nBase + r) * D_MODEL + k0 + c4 * 8;
            *(uint4*)&sAhi[r][c4 * 8] = *(const uint4*)(Ahi + gA);
            *(uint4*)&sAlo[r][c4 * 8] = *(const uint4*)(Alo + gA);
            *(uint4*)&sBhi[r][c4 * 8] = *(const uint4*)(BhiT + gB);
            *(uint4*)&sBlo[r][c4 * 8] = *(const uint4*)(BloT + gB);
        }
        __syncthreads();

        #pragma unroll
        for (int kk = 0; kk < GBK; kk += 16) {
            const uint32_t koff = kk * 2;
            uint32_t bh[8], bl[8];
            #pragma unroll
            for (int p = 0; p < 2; p++) {
                uint32_t r0, r1, r2, r3;
                ldmx4(bHiBase + p * 16 * SPAD * 2 + koff, r0, r1, r2, r3);
                bh[p * 4 + 0] = r0; bh[p * 4 + 1] = r2;
                bh[p * 4 + 2] = r1; bh[p * 4 + 3] = r3;
                ldmx4(bLoBase + p * 16 * SPAD * 2 + koff, r0, r1, r2, r3);
                bl[p * 4 + 0] = r0; bl[p * 4 + 1] = r2;
                bl[p * 4 + 2] = r1; bl[p * 4 + 3] = r3;
            }
            #pragma unroll
            for (int mi = 0; mi < 4; mi++) {
                uint32_t ah[4], al[4];
                ldmx4(aHiBase + mi * 16 * SPAD * 2 + koff, ah[0], ah[1], ah[2], ah[3]);
                ldmx4(aLoBase + mi * 16 * SPAD * 2 + koff, al[0], al[1], al[2], al[3]);
                #pragma unroll
                for (int ni = 0; ni < 4; ni++) {
                    const uint32_t b0h = bh[(ni >> 1) * 4 + (ni & 1) * 2];
                    const uint32_t b1h = bh[(ni >> 1) * 4 + (ni & 1) * 2 + 1];
                    const uint32_t b0l = bl[(ni >> 1) * 4 + (ni & 1) * 2];
                    const uint32_t b1l = bl[(ni >> 1) * 4 + (ni & 1) * 2 + 1];
                    mma16816(acc[mi][ni], ah, b0h, b1h);
                    mma16816(acc[mi][ni], ah, b0l, b1l);
                    mma16816(acc[mi][ni], al, b0h, b1h);
                }
            }
        }
        __syncthreads();
    }

    const int crow = lane >> 2;
    const int ccol = (lane & 3) * 2;
    #pragma unroll
    for (int mi = 0; mi < 4; mi++) {
        #pragma unroll
        for (int ni = 0; ni < 4; ni++) {
            const size_t row0 = rBase + warp_m * 64 + mi * 16 + crow;
            const size_t col = nBase + warp_n * 32 + ni * 8 + ccol;
            const float b0 = bias[col], b1 = bias[col + 1];
            float v00 = acc[mi][ni][0] + b0, v01 = acc[mi][ni][1] + b1;
            float v10 = acc[mi][ni][2] + b0, v11 = acc[mi][ni][3] + b1;
            if (Chi) {
                v00 *= scale; v01 *= scale; v10 *= scale; v11 *= scale;
                __nv_bfloat16 h00 = __float2bfloat16_rn(v00);
                __nv_bfloat16 h01 = __float2bfloat16_rn(v01);
                __nv_bfloat16 h10 = __float2bfloat16_rn(v10);
                __nv_bfloat16 h11 = __float2bfloat16_rn(v11);
                *(__nv_bfloat162*)(Chi + row0 * D_MODEL + col) = __nv_bfloat162(h00, h01);
                *(__nv_bfloat162*)(Chi + (row0 + 8) * D_MODEL + col) = __nv_bfloat162(h10, h11);
                *(__nv_bfloat162*)(Clo + row0 * D_MODEL + col) = __nv_bfloat162(
                    __float2bfloat16_rn(v00 - __bfloat162float(h00)),
                    __float2bfloat16_rn(v01 - __bfloat162float(h01)));
                *(__nv_bfloat162*)(Clo + (row0 + 8) * D_MODEL + col) = __nv_bfloat162(
                    __float2bfloat16_rn(v10 - __bfloat162float(h10)),
                    __float2bfloat16_rn(v11 - __bfloat162float(h11)));
            } else {
                *(float2*)(C + row0 * D_MODEL + col) = make_float2(v00, v01);
                *(float2*)(C + (row0 + 8) * D_MODEL + col) = make_float2(v10, v11);
            }
        }
    }
}

// ===================== tensor-core flash attention ==========================
// Grid: (SEQ/128 q-tiles, H*B). 8 warps x 16 q-rows. Key tile 64.
// Split-bf16 QK^T and PV (3 products each), fp32 online softmax.
// Output written pre-split (hi/lo) into g_Ahi/g_Alo for the O-projection.
#define AKT 64
#define ASTR 72

__global__ __launch_bounds__(256, 1) void attn_mma()
{
    __shared__ __nv_bfloat16 sKh[AKT][ASTR], sKl[AKT][ASTR];
    __shared__ __nv_bfloat16 sVh[AKT][ASTR], sVl[AKT][ASTR];

    const int qt = blockIdx.x;
    const int hb = blockIdx.y;
    const int h = hb / BATCH;
    const int b = hb % BATCH;
    const int tid = threadIdx.x;
    const int wid = tid >> 5;
    const int lane = tid & 31;

    const size_t headOff = (size_t)b * SEQ * D_MODEL + (size_t)h * D_K;
    const __nv_bfloat16* Qh = g_Qhi + headOff;
    const __nv_bfloat16* Ql = g_Qlo + headOff;
    const __nv_bfloat16* Kh = g_Khi + headOff;
    const __nv_bfloat16* Kl = g_Klo + headOff;
    const __nv_bfloat16* Vh = g_Vhi + headOff;
    const __nv_bfloat16* Vl = g_Vlo + headOff;

    // ---- prologue: stage Q tile (128x64 hi+lo) through the K/V buffers ----
    #pragma unroll
    for (int i = 0; i < 4; i++) {
        const int u = tid + i * 256;             // 0..1023
        const int r = u >> 3, c8 = (u & 7) * 8;
        const size_t g = (size_t)(qt * 128 + r) * D_MODEL + c8;
        __nv_bfloat16* dstH = (r < 64) ? &sKh[r][c8] : &sKl[r - 64][c8];
        __nv_bfloat16* dstL = (r < 64) ? &sVh[r][c8] : &sVl[r - 64][c8];
        *(uint4*)dstH = *(const uint4*)(Qh + g);
        *(uint4*)dstL = *(const uint4*)(Ql + g);
    }
    __syncthreads();

    uint32_t qh[4][4], ql[4][4];
    {
        const int rb = (wid & 3) * 16 + (lane & 15);
        const uint32_t offB = (uint32_t)((lane >> 4) * 16);
        const uint32_t aH = ((wid < 4) ? smem_u32_of(&sKh[rb][0]) : smem_u32_of(&sKl[rb][0])) + offB;
        const uint32_t aL = ((wid < 4) ? smem_u32_of(&sVh[rb][0]) : smem_u32_of(&sVl[rb][0])) + offB;
        #pragma unroll
        for (int kt = 0; kt < 4; kt++) {
            ldmx4(aH + kt * 32, qh[kt][0], qh[kt][1], qh[kt][2], qh[kt][3]);
            ldmx4(aL + kt * 32, ql[kt][0], ql[kt][1], ql[kt][2], ql[kt][3]);
        }
    }

    float m0 = -1e30f, m1 = -1e30f, l0 = 0.0f, l1 = 0.0f;
    float o[8][4] = {};

    // per-lane ldmatrix base offsets
    const uint32_t kBase = smem_u32_of(sKh) + (uint32_t)(((lane & 15) * ASTR + (lane >> 4) * 8) * 2);
    const uint32_t kBaseL = kBase + (uint32_t)(AKT * ASTR * 2);          // sKl follows sKh
    const uint32_t vBase = smem_u32_of(sVh) + (uint32_t)(((lane & 15) * ASTR + (lane >> 4) * 8) * 2);
    const uint32_t vBaseL = vBase + (uint32_t)(AKT * ASTR * 2);

    for (int kt0 = 0; kt0 < SEQ / AKT; kt0++) {
        __syncthreads();
        // ---- load K/V tile (64x64 hi+lo each) ----
        #pragma unroll
        for (int i = 0; i < 2; i++) {
            const int u = tid + i * 256;          // 0..511
            const int r = u >> 3, c8 = (u & 7) * 8;
            const size_t g = (size_t)(kt0 * AKT + r) * D_MODEL + c8;
            *(uint4*)&sKh[r][c8] = *(const uint4*)(Kh + g);
            *(uint4*)&sKl[r][c8] = *(const uint4*)(Kl + g);
            *(uint4*)&sVh[r][c8] = *(const uint4*)(Vh + g);
            *(uint4*)&sVl[r][c8] = *(const uint4*)(Vl + g);
        }
        __syncthreads();

        // ---- S = Q K^T (scale pre-folded into Q) ----
        float s[8][4] = {};
        #pragma unroll
        for (int np = 0; np < 4; np++) {
            #pragma unroll
            for (int kt = 0; kt < 4; kt++) {
                const uint32_t off = (uint32_t)(np * 16 * ASTR * 2 + kt * 32);
                uint32_t h0, h1, h2, h3, x0, x1, x2, x3;
                ldmx4(kBase + off, h0, h1, h2, h3);
                ldmx4(kBaseL + off, x0, x1, x2, x3);
                mma16816(s[2 * np],     qh[kt], h0, h2);
                mma16816(s[2 * np],     ql[kt], h0, h2);
                mma16816(s[2 * np],     qh[kt], x0, x2);
                mma16816(s[2 * np + 1], qh[kt], h1, h3);
                mma16816(s[2 * np + 1], ql[kt], h1, h3);
                mma16816(s[2 * np + 1], qh[kt], x1, x3);
            }
        }

        // ---- online softmax (rows r0=lane>>2, r1=r0+8) ----
        float mx0 = -1e30f, mx1 = -1e30f;
        #pragma unroll
        for (int nt = 0; nt < 8; nt++) {
            mx0 = fmaxf(mx0, fmaxf(s[nt][0], s[nt][1]));
            mx1 = fmaxf(mx1, fmaxf(s[nt][2], s[nt][3]));
        }
        mx0 = fmaxf(mx0, __shfl_xor_sync(0xffffffffu, mx0, 1));
        mx0 = fmaxf(mx0, __shfl_xor_sync(0xffffffffu, mx0, 2));
        mx1 = fmaxf(mx1, __shfl_xor_sync(0xffffffffu, mx1, 1));
        mx1 = fmaxf(mx1, __shfl_xor_sync(0xffffffffu, mx1, 2));
        const float m0n = fmaxf(m0, mx0), m1n = fmaxf(m1, mx1);
        const float a0 = __expf(m0 - m0n), a1 = __expf(m1 - m1n);
        float rs0 = 0.0f, rs1 = 0.0f;
        #pragma unroll
        for (int nt = 0; nt < 8; nt++) {
            s[nt][0] = __expf(s[nt][0] - m0n);
            s[nt][1] = __expf(s[nt][1] - m0n);
            s[nt][2] = __expf(s[nt][2] - m1n);
            s[nt][3] = __expf(s[nt][3] - m1n);
            rs0 += s[nt][0] + s[nt][1];
            rs1 += s[nt][2] + s[nt][3];
            o[nt][0] *= a0; o[nt][1] *= a0;
            o[nt][2] *= a1; o[nt][3] *= a1;
        }
        rs0 += __shfl_xor_sync(0xffffffffu, rs0, 1);
        rs0 += __shfl_xor_sync(0xffffffffu, rs0, 2);
        rs1 += __shfl_xor_sync(0xffffffffu, rs1, 1);
        rs1 += __shfl_xor_sync(0xffffffffu, rs1, 2);
        l0 = l0 * a0 + rs0;
        l1 = l1 * a1 + rs1;
        m0 = m0n; m1 = m1n;

        // ---- split P into hi/lo bf16 A-fragments ----
        uint32_t ph[4][4], pl[4][4];
        #pragma unroll
        for (int kt = 0; kt < 4; kt++) {
            const float* sa = s[2 * kt];
            const float* sb = s[2 * kt + 1];
            float hi;
            hi = __bfloat162float(__float2bfloat16_rn(sa[0]));
            float la0 = sa[0] - hi;
            hi = __bfloat162float(__float2bfloat16_rn(sa[1]));
            float la1 = sa[1] - hi;
            hi = __bfloat162float(__float2bfloat16_rn(sa[2]));
            float la2 = sa[2] - hi;
            hi = __bfloat162float(__float2bfloat16_rn(sa[3]));
            float la3 = sa[3] - hi;
            float lb0, lb1, lb2, lb3;
            hi = __bfloat162float(__float2bfloat16_rn(sb[0])); lb0 = sb[0] - hi;
            hi = __bfloat162float(__float2bfloat16_rn(sb[1])); lb1 = sb[1] - hi;
            hi = __bfloat162float(__float2bfloat16_rn(sb[2])); lb2 = sb[2] - hi;
            hi = __bfloat162float(__float2bfloat16_rn(sb[3])); lb3 = sb[3] - hi;
            ph[kt][0] = pack_bf16(sa[0], sa[1]);
            ph[kt][1] = pack_bf16(sa[2], sa[3]);
            ph[kt][2] = pack_bf16(sb[0], sb[1]);
            ph[kt][3] = pack_bf16(sb[2], sb[3]);
            pl[kt][0] = pack_bf16(la0, la1);
            pl[kt][1] = pack_bf16(la2, la3);
            pl[kt][2] = pack_bf16(lb0, lb1);
            pl[kt][3] = pack_bf16(lb2, lb3);
        }

        // ---- O += P @ V ----
        #pragma unroll
        for (int np = 0; np < 4; np++) {
            #pragma unroll
            for (int kt = 0; kt < 4; kt++) {
                const uint32_t off = (uint32_t)((kt * 16 * ASTR + np * 16) * 2);
                uint32_t h0, h1, h2, h3, x0, x1, x2, x3;
                ldmx4t(vBase + off, h0, h1, h2, h3);
                ldmx4t(vBaseL + off, x0, x1, x2, x3);
                mma16816(o[2 * np],     ph[kt], h0, h1);
                mma16816(o[2 * np],     pl[kt], h0, h1);
                mma16816(o[2 * np],     ph[kt], x0, x1);
                mma16816(o[2 * np + 1], ph[kt], h2, h3);
                mma16816(o[2 * np + 1], pl[kt], h2, h3);
                mma16816(o[2 * np + 1], ph[kt], x2, x3);
            }
        }
    }

    // ---- epilogue: normalize, split, write hi/lo for the O-projection ----
    const float inv0 = 1.0f / l0, inv1 = 1.0f / l1;
    const size_t row0 = (size_t)b * SEQ + qt * 128 + wid * 16 + (lane >> 2);
    const size_t row1 = row0 + 8;
    const int colB = h * D_K + (lane & 3) * 2;
    #pragma unroll
    for (int nt = 0; nt < 8; nt++) {
        const size_t c = colB + nt * 8;
        float v00 = o[nt][0] * inv0, v01 = o[nt][1] * inv0;
        float v10 = o[nt][2] * inv1, v11 = o[nt][3] * inv1;
        __nv_bfloat16 h00 = __float2bfloat16_rn(v00);
        __nv_bfloat16 h01 = __float2bfloat16_rn(v01);
        __nv_bfloat16 h10 = __float2bfloat16_rn(v10);
        __nv_bfloat16 h11 = __float2bfloat16_rn(v11);
        *(__nv_bfloat162*)(g_Ahi + row0 * D_MODEL + c) = __nv_bfloat162(h00, h01);
        *(__nv_bfloat162*)(g_Ahi + row1 * D_MODEL + c) = __nv_bfloat162(h10, h11);
        *(__nv_bfloat162*)(g_Alo + row0 * D_MODEL + c) = __nv_bfloat162(
            __float2bfloat16_rn(v00 - __bfloat162float(h00)),
            __float2bfloat16_rn(v01 - __bfloat162float(h01)));
        *(__nv_bfloat162*)(g_Alo + row1 * D_MODEL + c) = __nv_bfloat162(
            __float2bfloat16_rn(v10 - __bfloat162float(h10)),
            __float2bfloat16_rn(v11 - __bfloat162float(h11)));
    }
}

// ===================== launch ==============================================
extern "C" void kernel_launch(void* const* d_in, const int* in_sizes, int n_in,
                              void* d_out, int out_size)
{
    const float* q   = (const float*)d_in[0];
    const float* k   = (const float*)d_in[1];
    const float* v   = (const float*)d_in[2];
    const float* w_q = (const float*)d_in[3];
    const float* b_q = (const float*)d_in[4];
    const float* w_k = (const float*)d_in[5];
    const float* b_k = (const float*)d_in[6];
    const float* w_v = (const float*)d_in[7];
    const float* b_v = (const float*)d_in[8];
    const float* w_o = (const float*)d_in[9];
    const float* b_o = (const float*)d_in[10];
    float* out = (float*)d_out;

    __nv_bfloat16 *Ahi, *Alo, *Whi, *Wlo, *Qhi, *Qlo, *Khi, *Klo, *Vhi, *Vlo;
    cudaGetSymbolAddress((void**)&Ahi, g_Ahi);
    cudaGetSymbolAddress((void**)&Alo, g_Alo);
    cudaGetSymbolAddress((void**)&Whi, g_WhiT);
    cudaGetSymbolAddress((void**)&Wlo, g_WloT);
    cudaGetSymbolAddress((void**)&Qhi, g_Qhi);
    cudaGetSymbolAddress((void**)&Qlo, g_Qlo);
    cudaGetSymbolAddress((void**)&Khi, g_Khi);
    cudaGetSymbolAddress((void**)&Klo, g_Klo);
    cudaGetSymbolAddress((void**)&Vhi, g_Vhi);
    cudaGetSymbolAddress((void**)&Vlo, g_Vlo);

    const dim3 wgrid(D_MODEL / 32, D_MODEL / 32), wblk(32, 8);
    const int n4 = MROWS * D_MODEL / 4;
    const int splitBlocks = n4 / 256;
    const dim3 ggrid(D_MODEL / GBN, MROWS / GBM);

    const float qscale = 0.125f;   // 1/sqrt(d_k)

    // Q projection -> split bf16 (scale folded in)
    wsplit_kernel<<<wgrid, wblk>>>(w_q, Whi, Wlo);
    split_kernel<<<splitBlocks, 256>>>(q, Ahi, Alo, n4);
    gemm_tc<<<ggrid, 256>>>(Ahi, Alo, Whi, Wlo, b_q, nullptr, Qhi, Qlo, qscale);
    // K projection
    wsplit_kernel<<<wgrid, wblk>>>(w_k, Whi, Wlo);
    split_kernel<<<splitBlocks, 256>>>(k, Ahi, Alo, n4);
    gemm_tc<<<ggrid, 256>>>(Ahi, Alo, Whi, Wlo, b_k, nullptr, Khi, Klo, 1.0f);
    // V projection
    wsplit_kernel<<<wgrid, wblk>>>(w_v, Whi, Wlo);
    split_kernel<<<splitBlocks, 256>>>(v, Ahi, Alo, n4);
    gemm_tc<<<ggrid, 256>>>(Ahi, Alo, Whi, Wlo, b_v, nullptr, Vhi, Vlo, 1.0f);

    // attention (writes split output straight into Ahi/Alo)
    dim3 attnGrid(SEQ / 128, N_HEAD * BATCH);
    attn_mma<<<attnGrid, 256>>>();

    // output projection (fp32 out)
    wsplit_kernel<<<wgrid, wblk>>>(w_o, Whi, Wlo);
    gemm_tc<<<ggrid, 256>>>(Ahi, Alo, Whi, Wlo, b_o, out, nullptr, nullptr, 1.0f);
}

// round 5
// speedup vs baseline: 2.3916x; 1.0651x over previous
#include <cuda_runtime.h>
#include <cuda_bf16.h>
#include <cstdint>
#include <math.h>

#define D_MODEL 1024
#define N_HEAD  16
#define D_K     64
#define BATCH   2
#define SEQ     2048
#define MROWS   (BATCH * SEQ)   // 4096
#define WELEM   (D_MODEL * D_MODEL)
#define XELEM   (MROWS * D_MODEL)

// ===================== scratch (allocation-free: device globals) ============
__device__ __nv_bfloat16 g_W4hi[4 * WELEM];   // 4 transposed-split weights
__device__ __nv_bfloat16 g_W4lo[4 * WELEM];
__device__ __nv_bfloat16 g_X3hi[3 * XELEM];   // split q,k,v inputs
__device__ __nv_bfloat16 g_X3lo[3 * XELEM];
__device__ __nv_bfloat16 g_Qhi[XELEM], g_Qlo[XELEM];
__device__ __nv_bfloat16 g_Khi[XELEM], g_Klo[XELEM];
__device__ __nv_bfloat16 g_Vhi[XELEM], g_Vlo[XELEM];
__device__ __nv_bfloat16 g_Ahi[XELEM], g_Alo[XELEM];   // attention output (split)

// ===================== helpers ==============================================
__device__ __forceinline__ uint32_t smem_u32_of(const void* p) {
    uint32_t a;
    asm("{ .reg .u64 t; cvta.to.shared.u64 t, %1; cvt.u32.u64 %0, t; }"
        : "=r"(a) : "l"(p));
    return a;
}
__device__ __forceinline__ void ldmx4(uint32_t addr, uint32_t& r0, uint32_t& r1,
                                      uint32_t& r2, uint32_t& r3) {
    asm volatile("ldmatrix.sync.aligned.m8n8.x4.shared.b16 {%0,%1,%2,%3}, [%4];"
                 : "=r"(r0), "=r"(r1), "=r"(r2), "=r"(r3) : "r"(addr));
}
__device__ __forceinline__ void ldmx4t(uint32_t addr, uint32_t& r0, uint32_t& r1,
                                       uint32_t& r2, uint32_t& r3) {
    asm volatile("ldmatrix.sync.aligned.m8n8.x4.trans.shared.b16 {%0,%1,%2,%3}, [%4];"
                 : "=r"(r0), "=r"(r1), "=r"(r2), "=r"(r3) : "r"(addr));
}
__device__ __forceinline__ void mma16816(float* c, const uint32_t* a,
                                         uint32_t b0, uint32_t b1) {
    asm volatile(
        "mma.sync.aligned.m16n8k16.row.col.f32.bf16.bf16.f32 "
        "{%0,%1,%2,%3}, {%4,%5,%6,%7}, {%8,%9}, {%0,%1,%2,%3};"
        : "+f"(c[0]), "+f"(c[1]), "+f"(c[2]), "+f"(c[3])
        : "r"(a[0]), "r"(a[1]), "r"(a[2]), "r"(a[3]), "r"(b0), "r"(b1));
}
__device__ __forceinline__ uint32_t pack_bf16(float x, float y) {
    __nv_bfloat162 t = __floats2bfloat162_rn(x, y);
    return *(uint32_t*)&t;
}
__device__ __forceinline__ void cp16(uint32_t dst, const void* src) {
    asm volatile("cp.async.cg.shared.global [%0], [%1], 16;"
                 :: "r"(dst), "l"(src) : "memory");
}
#define CP_COMMIT()  asm volatile("cp.async.commit_group;" ::: "memory")
#define CP_WAIT1()   asm volatile("cp.async.wait_group 1;" ::: "memory")
#define CP_WAIT0()   asm volatile("cp.async.wait_group 0;" ::: "memory")

// ===================== fused conversions ====================================
// 3 fp32 inputs -> split bf16 (hi/lo), one launch
__global__ __launch_bounds__(256) void split_all(
    const float* __restrict__ x0, const float* __restrict__ x1,
    const float* __restrict__ x2)
{
    const int which = blockIdx.y;
    const float* x = (which == 0) ? x0 : (which == 1) ? x1 : x2;
    __nv_bfloat16* hi = g_X3hi + (size_t)which * XELEM;
    __nv_bfloat16* lo = g_X3lo + (size_t)which * XELEM;
    const int i = blockIdx.x * 256 + threadIdx.x;     // float4 index
    float4 v = ((const float4*)x)[i];
    __nv_bfloat16 h0 = __float2bfloat16_rn(v.x);
    __nv_bfloat16 h1 = __float2bfloat16_rn(v.y);
    __nv_bfloat16 h2 = __float2bfloat16_rn(v.z);
    __nv_bfloat16 h3 = __float2bfloat16_rn(v.w);
    ((__nv_bfloat162*)hi)[i * 2 + 0] = __nv_bfloat162(h0, h1);
    ((__nv_bfloat162*)hi)[i * 2 + 1] = __nv_bfloat162(h2, h3);
    ((__nv_bfloat162*)lo)[i * 2 + 0] = __nv_bfloat162(
        __float2bfloat16_rn(v.x - __bfloat162float(h0)),
        __float2bfloat16_rn(v.y - __bfloat162float(h1)));
    ((__nv_bfloat162*)lo)[i * 2 + 1] = __nv_bfloat162(
        __float2bfloat16_rn(v.z - __bfloat162float(h2)),
        __float2bfloat16_rn(v.w - __bfloat162float(h3)));
}

// 4 weights [K][N] fp32 -> [N][K] split bf16, one launch (blockIdx.z selects)
__global__ __launch_bounds__(256) void wsplit_all(
    const float* __restrict__ w0, const float* __restrict__ w1,
    const float* __restrict__ w2, const float* __restrict__ w3)
{
    __shared__ float t[32][33];
    const int z = blockIdx.z;
    const float* W = (z == 0) ? w0 : (z == 1) ? w1 : (z == 2) ? w2 : w3;
    __nv_bfloat16* hiT = g_W4hi + (size_t)z * WELEM;
    __nv_bfloat16* loT = g_W4lo + (size_t)z * WELEM;
    const int nBase = blockIdx.x * 32, kBase = blockIdx.y * 32;
    const int tx = threadIdx.x, ty = threadIdx.y;     // 32 x 8
    #pragma unroll
    for (int r = 0; r < 4; r++)
        t[ty + 8 * r][tx] = W[(size_t)(kBase + ty + 8 * r) * D_MODEL + nBase + tx];
    __syncthreads();
    #pragma unroll
    for (int r = 0; r < 4; r++) {
        float v = t[tx][ty + 8 * r];
        __nv_bfloat16 h = __float2bfloat16_rn(v);
        size_t o = (size_t)(nBase + ty + 8 * r) * D_MODEL + kBase + tx;
        hiT[o] = h;
        loT[o] = __float2bfloat16_rn(v - __bfloat162float(h));
    }
}

// ===================== HMMA split-bf16 GEMM (cp.async 2-stage) ==============
#define GBM 128
#define GBN 128
#define GBK 32
#define SPAD 40
#define GT_TILE (GBM * SPAD)              // elems per tile (5120)
#define GT_STAGE (4 * GT_TILE)            // elems per stage (20480)
#define GEMM_SMEM (2 * GT_STAGE * 2)      // bytes (81920)
#define NCH (D_MODEL / GBK)               // 32

__global__ __launch_bounds__(256, 2) void gemm_tc(
    const __nv_bfloat16* __restrict__ Ahi, const __nv_bfloat16* __restrict__ Alo,
    const __nv_bfloat16* __restrict__ BhiT, const __nv_bfloat16* __restrict__ BloT,
    const float* __restrict__ bias, float* __restrict__ C,
    __nv_bfloat16* __restrict__ Chi, __nv_bfloat16* __restrict__ Clo, float scale)
{
    extern __shared__ __nv_bfloat16 ds[];
    const uint32_t dsb = smem_u32_of(ds);

    const int tid = threadIdx.x;
    const int wid = tid >> 5;
    const int lane = tid & 31;
    const int warp_m = wid & 1;
    const int warp_n = wid >> 1;

    const size_t rBase = (size_t)blockIdx.y * GBM;
    const size_t nBase = (size_t)blockIdx.x * GBN;

    float acc[4][4][4] = {};

    // per-lane ldmatrix bases for each stage
    const int lrow = lane & 15;
    const int lcol8 = (lane >> 4) * 8;
    uint32_t aHiB[2], aLoB[2], bHiB[2], bLoB[2];
    #pragma unroll
    for (int s = 0; s < 2; s++) {
        const uint32_t sb = dsb + (uint32_t)(s * GT_STAGE * 2);
        aHiB[s] = sb + 0 * GT_TILE * 2 + ((warp_m * 64 + lrow) * SPAD + lcol8) * 2;
        aLoB[s] = sb + 1 * GT_TILE * 2 + ((warp_m * 64 + lrow) * SPAD + lcol8) * 2;
        bHiB[s] = sb + 2 * GT_TILE * 2 + ((warp_n * 32 + lrow) * SPAD + lcol8) * 2;
        bLoB[s] = sb + 3 * GT_TILE * 2 + ((warp_n * 32 + lrow) * SPAD + lcol8) * 2;
    }

    // loader lane geometry (per thread: 2 rows x 4 tiles = 8 cp16)
    const int ldr = tid >> 2;              // base row (0..63), +64 second pass
    const int ldc = (tid & 3) * 8;         // 0,8,16,24 elems

    // prefetch chunk 0 -> stage 0
    {
        #pragma unroll
        for (int it = 0; it < 2; it++) {
            const int r = ldr + it * 64;
            const size_t gA = (rBase + r) * D_MODEL + ldc;
            const size_t gB = (nBase + r) * D_MODEL + ldc;
            const uint32_t so = (uint32_t)((r * SPAD + ldc) * 2);
            cp16(dsb + 0 * GT_TILE * 2 + so, Ahi + gA);
            cp16(dsb + 1 * GT_TILE * 2 + so, Alo + gA);
            cp16(dsb + 2 * GT_TILE * 2 + so, BhiT + gB);
            cp16(dsb + 3 * GT_TILE * 2 + so, BloT + gB);
        }
        CP_COMMIT();
    }

    for (int c = 0; c < NCH; c++) {
        if (c + 1 < NCH) {
            const int k0 = (c + 1) * GBK;
            const uint32_t sb = dsb + (uint32_t)(((c + 1) & 1) * GT_STAGE * 2);
            #pragma unroll
            for (int it = 0; it < 2; it++) {
                const int r = ldr + it * 64;
                const size_t gA = (rBase + r) * D_MODEL + k0 + ldc;
                const size_t gB = (nBase + r) * D_MODEL + k0 + ldc;
                const uint32_t so = (uint32_t)((r * SPAD + ldc) * 2);
                cp16(sb + 0 * GT_TILE * 2 + so, Ahi + gA);
                cp16(sb + 1 * GT_TILE * 2 + so, Alo + gA);
                cp16(sb + 2 * GT_TILE * 2 + so, BhiT + gB);
                cp16(sb + 3 * GT_TILE * 2 + so, BloT + gB);
            }
            CP_COMMIT();
            CP_WAIT1();
        } else {
            CP_WAIT0();
        }
        __syncthreads();

        const int s = c & 1;
        #pragma unroll
        for (int kk = 0; kk < GBK; kk += 16) {
            const uint32_t koff = kk * 2;
            uint32_t bh[8], bl[8];
            #pragma unroll
            for (int p = 0; p < 2; p++) {
                uint32_t r0, r1, r2, r3;
                ldmx4(bHiB[s] + p * 16 * SPAD * 2 + koff, r0, r1, r2, r3);
                bh[p * 4 + 0] = r0; bh[p * 4 + 1] = r2;
                bh[p * 4 + 2] = r1; bh[p * 4 + 3] = r3;
                ldmx4(bLoB[s] + p * 16 * SPAD * 2 + koff, r0, r1, r2, r3);
                bl[p * 4 + 0] = r0; bl[p * 4 + 1] = r2;
                bl[p * 4 + 2] = r1; bl[p * 4 + 3] = r3;
            }
            #pragma unroll
            for (int mi = 0; mi < 4; mi++) {
                uint32_t ah[4], al[4];
                ldmx4(aHiB[s] + mi * 16 * SPAD * 2 + koff, ah[0], ah[1], ah[2], ah[3]);
                ldmx4(aLoB[s] + mi * 16 * SPAD * 2 + koff, al[0], al[1], al[2], al[3]);
                #pragma unroll
                for (int ni = 0; ni < 4; ni++) {
                    const uint32_t b0h = bh[(ni >> 1) * 4 + (ni & 1) * 2];
                    const uint32_t b1h = bh[(ni >> 1) * 4 + (ni & 1) * 2 + 1];
                    const uint32_t b0l = bl[(ni >> 1) * 4 + (ni & 1) * 2];
                    const uint32_t b1l = bl[(ni >> 1) * 4 + (ni & 1) * 2 + 1];
                    mma16816(acc[mi][ni], ah, b0h, b1h);
                    mma16816(acc[mi][ni], ah, b0l, b1l);
                    mma16816(acc[mi][ni], al, b0h, b1h);
                }
            }
        }
        __syncthreads();
    }

    const int crow = lane >> 2;
    const int ccol = (lane & 3) * 2;
    #pragma unroll
    for (int mi = 0; mi < 4; mi++) {
        #pragma unroll
        for (int ni = 0; ni < 4; ni++) {
            const size_t row0 = rBase + warp_m * 64 + mi * 16 + crow;
            const size_t col = nBase + warp_n * 32 + ni * 8 + ccol;
            const float b0 = bias[col], b1 = bias[col + 1];
            float v00 = acc[mi][ni][0] + b0, v01 = acc[mi][ni][1] + b1;
            float v10 = acc[mi][ni][2] + b0, v11 = acc[mi][ni][3] + b1;
            if (Chi) {
                v00 *= scale; v01 *= scale; v10 *= scale; v11 *= scale;
                __nv_bfloat16 h00 = __float2bfloat16_rn(v00);
                __nv_bfloat16 h01 = __float2bfloat16_rn(v01);
                __nv_bfloat16 h10 = __float2bfloat16_rn(v10);
                __nv_bfloat16 h11 = __float2bfloat16_rn(v11);
                *(__nv_bfloat162*)(Chi + row0 * D_MODEL + col) = __nv_bfloat162(h00, h01);
                *(__nv_bfloat162*)(Chi + (row0 + 8) * D_MODEL + col) = __nv_bfloat162(h10, h11);
                *(__nv_bfloat162*)(Clo + row0 * D_MODEL + col) = __nv_bfloat162(
                    __float2bfloat16_rn(v00 - __bfloat162float(h00)),
                    __float2bfloat16_rn(v01 - __bfloat162float(h01)));
                *(__nv_bfloat162*)(Clo + (row0 + 8) * D_MODEL + col) = __nv_bfloat162(
                    __float2bfloat16_rn(v10 - __bfloat162float(h10)),
                    __float2bfloat16_rn(v11 - __bfloat162float(h11)));
            } else {
                *(float2*)(C + row0 * D_MODEL + col) = make_float2(v00, v01);
                *(float2*)(C + (row0 + 8) * D_MODEL + col) = make_float2(v10, v11);
            }
        }
    }
}

// ===================== tensor-core flash attention (cp.async 2-stage) =======
#define AKT 64
#define ASTR 72
#define AT_TILE (AKT * ASTR)               // 4608 elems
#define AT_STAGE (4 * AT_TILE)             // Kh,Kl,Vh,Vl
#define ATTN_SMEM (2 * AT_STAGE * 2)       // 73728 bytes
#define NKT (SEQ / AKT)                    // 32

__global__ __launch_bounds__(256, 1) void attn_mma()
{
    extern __shared__ __nv_bfloat16 as_[];
    const uint32_t asb = smem_u32_of(as_);

    const int qt = blockIdx.x;
    const int hb = blockIdx.y;
    const int h = hb / BATCH;
    const int b = hb % BATCH;
    const int tid = threadIdx.x;
    const int wid = tid >> 5;
    const int lane = tid & 31;

    const size_t headOff = (size_t)b * SEQ * D_MODEL + (size_t)h * D_K;
    const __nv_bfloat16* Qh = g_Qhi + headOff;
    const __nv_bfloat16* Ql = g_Qlo + headOff;
    const __nv_bfloat16* Kh = g_Khi + headOff;
    const __nv_bfloat16* Kl = g_Klo + headOff;
    const __nv_bfloat16* Vh = g_Vhi + headOff;
    const __nv_bfloat16* Vl = g_Vlo + headOff;

    // ---- prologue: stage Q (128x64 hi+lo) through stage-0 tile slots ----
    #pragma unroll
    for (int i = 0; i < 4; i++) {
        const int u = tid + i * 256;              // 0..1023
        const int r = u >> 3, c8 = (u & 7) * 8;
        const size_t g = (size_t)(qt * 128 + r) * D_MODEL + c8;
        // Qhi rows 0-63 -> slot0 (Kh), 64-127 -> slot1 (Kl)
        // Qlo rows 0-63 -> slot2 (Vh), 64-127 -> slot3 (Vl)
        const int slotH = (r < 64) ? 0 : 1;
        const int slotL = (r < 64) ? 2 : 3;
        const int rr = r & 63;
        *(uint4*)(as_ + slotH * AT_TILE + rr * ASTR + c8) = *(const uint4*)(Qh + g);
        *(uint4*)(as_ + slotL * AT_TILE + rr * ASTR + c8) = *(const uint4*)(Ql + g);
    }
    __syncthreads();

    uint32_t qh[4][4], ql[4][4];
    {
        const int rb = (wid & 3) * 16 + (lane & 15);
        const uint32_t offB = (uint32_t)((lane >> 4) * 16 + rb * ASTR * 2);
        const uint32_t aH = asb + ((wid < 4) ? 0 : AT_TILE * 2) + offB;
        const uint32_t aL = asb + ((wid < 4) ? 2 * AT_TILE * 2 : 3 * AT_TILE * 2) + offB;
        #pragma unroll
        for (int kt = 0; kt < 4; kt++) {
            ldmx4(aH + kt * 32, qh[kt][0], qh[kt][1], qh[kt][2], qh[kt][3]);
            ldmx4(aL + kt * 32, ql[kt][0], ql[kt][1], ql[kt][2], ql[kt][3]);
        }
    }
    __syncthreads();   // everyone done reading Q before cp.async overwrites

    float m0 = -1e30f, m1 = -1e30f, l0 = 0.0f, l1 = 0.0f;
    float o[8][4] = {};

    // per-lane ldmatrix bases per stage
    uint32_t kB[2], kBL[2], vB[2], vBL[2];
    #pragma unroll
    for (int s = 0; s < 2; s++) {
        const uint32_t sb = asb + (uint32_t)(s * AT_STAGE * 2);
        const uint32_t lo = (uint32_t)(((lane & 15) * ASTR + (lane >> 4) * 8) * 2);
        kB[s]  = sb + lo;
        kBL[s] = sb + AT_TILE * 2 + lo;
        vB[s]  = sb + 2 * AT_TILE * 2 + lo;
        vBL[s] = sb + 3 * AT_TILE * 2 + lo;
    }

    // loader geometry: per thread 2 rows x 4 tiles = 8 cp16 per stage
    const int ldr = tid >> 2;              // 0..63 (one pass: 64 rows, 4 chunks)
    const int ldc = (tid & 3) * 8;         // wait: 64 elems/row = 4 x16B chunks? 64*2=128B = 8 chunks
    // 64 bf16 per row = 128 bytes = 8 x 16B; 256 threads, 64 rows x 8 chunks x 4 tiles
    // = 2048 cp16 -> 8 per thread: thread covers (row = tid>>2) chunks (tid&3) and (tid&3)+4.

    // prefetch kt 0 -> stage 0
    {
        #pragma unroll
        for (int it = 0; it < 2; it++) {
            const int c8 = (ldc + it * 32);               // elem offset (0..56 by 8)
            const size_t g = (size_t)(0 * AKT + ldr) * D_MODEL + c8;
            const uint32_t so = (uint32_t)((ldr * ASTR + c8) * 2);
            cp16(asb + 0 * AT_TILE * 2 + so, Kh + g);
            cp16(asb + 1 * AT_TILE * 2 + so, Kl + g);
            cp16(asb + 2 * AT_TILE * 2 + so, Vh + g);
            cp16(asb + 3 * AT_TILE * 2 + so, Vl + g);
        }
        CP_COMMIT();
    }

    for (int kt0 = 0; kt0 < NKT; kt0++) {
        if (kt0 + 1 < NKT) {
            const uint32_t sb = asb + (uint32_t)(((kt0 + 1) & 1) * AT_STAGE * 2);
            #pragma unroll
            for (int it = 0; it < 2; it++) {
                const int c8 = (ldc + it * 32);
                const size_t g = (size_t)((kt0 + 1) * AKT + ldr) * D_MODEL + c8;
                const uint32_t so = (uint32_t)((ldr * ASTR + c8) * 2);
                cp16(sb + 0 * AT_TILE * 2 + so, Kh + g);
                cp16(sb + 1 * AT_TILE * 2 + so, Kl + g);
                cp16(sb + 2 * AT_TILE * 2 + so, Vh + g);
                cp16(sb + 3 * AT_TILE * 2 + so, Vl + g);
            }
            CP_COMMIT();
            CP_WAIT1();
        } else {
            CP_WAIT0();
        }
        __syncthreads();
        const int s = kt0 & 1;

        // ---- S = Q K^T (scale pre-folded into Q) ----
        float sc[8][4] = {};
        #pragma unroll
        for (int np = 0; np < 4; np++) {
            #pragma unroll
            for (int kt = 0; kt < 4; kt++) {
                const uint32_t off = (uint32_t)(np * 16 * ASTR * 2 + kt * 32);
                uint32_t h0, h1, h2, h3, x0, x1, x2, x3;
                ldmx4(kB[s] + off, h0, h1, h2, h3);
                ldmx4(kBL[s] + off, x0, x1, x2, x3);
                mma16816(sc[2 * np],     qh[kt], h0, h2);
                mma16816(sc[2 * np],     ql[kt], h0, h2);
                mma16816(sc[2 * np],     qh[kt], x0, x2);
                mma16816(sc[2 * np + 1], qh[kt], h1, h3);
                mma16816(sc[2 * np + 1], ql[kt], h1, h3);
                mma16816(sc[2 * np + 1], qh[kt], x1, x3);
            }
        }

        // ---- online softmax ----
        float mx0 = -1e30f, mx1 = -1e30f;
        #pragma unroll
        for (int nt = 0; nt < 8; nt++) {
            mx0 = fmaxf(mx0, fmaxf(sc[nt][0], sc[nt][1]));
            mx1 = fmaxf(mx1, fmaxf(sc[nt][2], sc[nt][3]));
        }
        mx0 = fmaxf(mx0, __shfl_xor_sync(0xffffffffu, mx0, 1));
        mx0 = fmaxf(mx0, __shfl_xor_sync(0xffffffffu, mx0, 2));
        mx1 = fmaxf(mx1, __shfl_xor_sync(0xffffffffu, mx1, 1));
        mx1 = fmaxf(mx1, __shfl_xor_sync(0xffffffffu, mx1, 2));
        const float m0n = fmaxf(m0, mx0), m1n = fmaxf(m1, mx1);
        const float a0 = __expf(m0 - m0n), a1 = __expf(m1 - m1n);
        float rs0 = 0.0f, rs1 = 0.0f;
        #pragma unroll
        for (int nt = 0; nt < 8; nt++) {
            sc[nt][0] = __expf(sc[nt][0] - m0n);
            sc[nt][1] = __expf(sc[nt][1] - m0n);
            sc[nt][2] = __expf(sc[nt][2] - m1n);
            sc[nt][3] = __expf(sc[nt][3] - m1n);
            rs0 += sc[nt][0] + sc[nt][1];
            rs1 += sc[nt][2] + sc[nt][3];
            o[nt][0] *= a0; o[nt][1] *= a0;
            o[nt][2] *= a1; o[nt][3] *= a1;
        }
        rs0 += __shfl_xor_sync(0xffffffffu, rs0, 1);
        rs0 += __shfl_xor_sync(0xffffffffu, rs0, 2);
        rs1 += __shfl_xor_sync(0xffffffffu, rs1, 1);
        rs1 += __shfl_xor_sync(0xffffffffu, rs1, 2);
        l0 = l0 * a0 + rs0;
        l1 = l1 * a1 + rs1;
        m0 = m0n; m1 = m1n;

        // ---- split P ----
        uint32_t ph[4][4], pl[4][4];
        #pragma unroll
        for (int kt = 0; kt < 4; kt++) {
            const float* sa = sc[2 * kt];
            const float* sb2 = sc[2 * kt + 1];
            float hv;
            float la0, la1, la2, la3, lb0, lb1, lb2, lb3;
            hv = __bfloat162float(__float2bfloat16_rn(sa[0])); la0 = sa[0] - hv;
            hv = __bfloat162float(__float2bfloat16_rn(sa[1])); la1 = sa[1] - hv;
            hv = __bfloat162float(__float2bfloat16_rn(sa[2])); la2 = sa[2] - hv;
            hv = __bfloat162float(__float2bfloat16_rn(sa[3])); la3 = sa[3] - hv;
            hv = __bfloat162float(__float2bfloat16_rn(sb2[0])); lb0 = sb2[0] - hv;
            hv = __bfloat162float(__float2bfloat16_rn(sb2[1])); lb1 = sb2[1] - hv;
            hv = __bfloat162float(__float2bfloat16_rn(sb2[2])); lb2 = sb2[2] - hv;
            hv = __bfloat162float(__float2bfloat16_rn(sb2[3])); lb3 = sb2[3] - hv;
            ph[kt][0] = pack_bf16(sa[0], sa[1]);
            ph[kt][1] = pack_bf16(sa[2], sa[3]);
            ph[kt][2] = pack_bf16(sb2[0], sb2[1]);
            ph[kt][3] = pack_bf16(sb2[2], sb2[3]);
            pl[kt][0] = pack_bf16(la0, la1);
            pl[kt][1] = pack_bf16(la2, la3);
            pl[kt][2] = pack_bf16(lb0, lb1);
            pl[kt][3] = pack_bf16(lb2, lb3);
        }

        // ---- O += P @ V ----
        #pragma unroll
        for (int np = 0; np < 4; np++) {
            #pragma unroll
            for (int kt = 0; kt < 4; kt++) {
                const uint32_t off = (uint32_t)((kt * 16 * ASTR + np * 16) * 2);
                uint32_t h0, h1, h2, h3, x0, x1, x2, x3;
                ldmx4t(vB[s] + off, h0, h1, h2, h3);
                ldmx4t(vBL[s] + off, x0, x1, x2, x3);
                mma16816(o[2 * np],     ph[kt], h0, h1);
                mma16816(o[2 * np],     pl[kt], h0, h1);
                mma16816(o[2 * np],     ph[kt], x0, x1);
                mma16816(o[2 * np + 1], ph[kt], h2, h3);
                mma16816(o[2 * np + 1], pl[kt], h2, h3);
                mma16816(o[2 * np + 1], ph[kt], x2, x3);
            }
        }
        __syncthreads();
    }

    // ---- epilogue: normalize, split, write for the O-projection ----
    const float inv0 = 1.0f / l0, inv1 = 1.0f / l1;
    const size_t row0 = (size_t)b * SEQ + qt * 128 + wid * 16 + (lane >> 2);
    const size_t row1 = row0 + 8;
    const int colB = h * D_K + (lane & 3) * 2;
    #pragma unroll
    for (int nt = 0; nt < 8; nt++) {
        const size_t c = colB + nt * 8;
        float v00 = o[nt][0] * inv0, v01 = o[nt][1] * inv0;
        float v10 = o[nt][2] * inv1, v11 = o[nt][3] * inv1;
        __nv_bfloat16 h00 = __float2bfloat16_rn(v00);
        __nv_bfloat16 h01 = __float2bfloat16_rn(v01);
        __nv_bfloat16 h10 = __float2bfloat16_rn(v10);
        __nv_bfloat16 h11 = __float2bfloat16_rn(v11);
        *(__nv_bfloat162*)(g_Ahi + row0 * D_MODEL + c) = __nv_bfloat162(h00, h01);
        *(__nv_bfloat162*)(g_Ahi + row1 * D_MODEL + c) = __nv_bfloat162(h10, h11);
        *(__nv_bfloat162*)(g_Alo + row0 * D_MODEL + c) = __nv_bfloat162(
            __float2bfloat16_rn(v00 - __bfloat162float(h00)),
            __float2bfloat16_rn(v01 - __bfloat162float(h01)));
        *(__nv_bfloat162*)(g_Alo + row1 * D_MODEL + c) = __nv_bfloat162(
            __float2bfloat16_rn(v10 - __bfloat162float(h10)),
            __float2bfloat16_rn(v11 - __bfloat162float(h11)));
    }
}

// ===================== launch ==============================================
extern "C" void kernel_launch(void* const* d_in, const int* in_sizes, int n_in,
                              void* d_out, int out_size)
{
    const float* q   = (const float*)d_in[0];
    const float* k   = (const float*)d_in[1];
    const float* v   = (const float*)d_in[2];
    const float* w_q = (const float*)d_in[3];
    const float* b_q = (const float*)d_in[4];
    const float* w_k = (const float*)d_in[5];
    const float* b_k = (const float*)d_in[6];
    const float* w_v = (const float*)d_in[7];
    const float* b_v = (const float*)d_in[8];
    const float* w_o = (const float*)d_in[9];
    const float* b_o = (const float*)d_in[10];
    float* out = (float*)d_out;

    __nv_bfloat16 *W4hi, *W4lo, *X3hi, *X3lo;
    __nv_bfloat16 *Qhi, *Qlo, *Khi, *Klo, *Vhi, *Vlo, *Ahi, *Alo;
    cudaGetSymbolAddress((void**)&W4hi, g_W4hi);
    cudaGetSymbolAddress((void**)&W4lo, g_W4lo);
    cudaGetSymbolAddress((void**)&X3hi, g_X3hi);
    cudaGetSymbolAddress((void**)&X3lo, g_X3lo);
    cudaGetSymbolAddress((void**)&Qhi, g_Qhi);
    cudaGetSymbolAddress((void**)&Qlo, g_Qlo);
    cudaGetSymbolAddress((void**)&Khi, g_Khi);
    cudaGetSymbolAddress((void**)&Klo, g_Klo);
    cudaGetSymbolAddress((void**)&Vhi, g_Vhi);
    cudaGetSymbolAddress((void**)&Vlo, g_Vlo);
    cudaGetSymbolAddress((void**)&Ahi, g_Ahi);
    cudaGetSymbolAddress((void**)&Alo, g_Alo);

    cudaFuncSetAttribute(gemm_tc, cudaFuncAttributeMaxDynamicSharedMemorySize, GEMM_SMEM);
    cudaFuncSetAttribute(attn_mma, cudaFuncAttributeMaxDynamicSharedMemorySize, ATTN_SMEM);

    const int n4 = XELEM / 4;
    const dim3 ggrid(D_MODEL / GBN, MROWS / GBM);     // (8, 32)
    const float qscale = 0.125f;                      // 1/sqrt(d_k)

    // conversions (fused)
    wsplit_all<<<dim3(32, 32, 4), dim3(32, 8)>>>(w_q, w_k, w_v, w_o);
    split_all<<<dim3(n4 / 256, 3), 256>>>(q, k, v);

    // projections
    gemm_tc<<<ggrid, 256, GEMM_SMEM>>>(X3hi, X3lo, W4hi, W4lo,
                                       b_q, nullptr, Qhi, Qlo, qscale);
    gemm_tc<<<ggrid, 256, GEMM_SMEM>>>(X3hi + XELEM, X3lo + XELEM,
                                       W4hi + WELEM, W4lo + WELEM,
                                       b_k, nullptr, Khi, Klo, 1.0f);
    gemm_tc<<<ggrid, 256, GEMM_SMEM>>>(X3hi + 2 * XELEM, X3lo + 2 * XELEM,
                                       W4hi + 2 * WELEM, W4lo + 2 * WELEM,
                                       b_v, nullptr, Vhi, Vlo, 1.0f);

    // attention
    attn_mma<<<dim3(SEQ / 128, N_HEAD * BATCH), 256, ATTN_SMEM>>>();

    // output projection
    gemm_tc<<<ggrid, 256, GEMM_SMEM>>>(Ahi, Alo, W4hi + 3 * WELEM, W4lo + 3 * WELEM,
                                       b_o, out, nullptr, nullptr, 1.0f);
}

// round 6
// speedup vs baseline: 2.6983x; 1.1282x over previous
#include <cuda_runtime.h>
#include <cuda_bf16.h>
#include <cstdint>
#include <math.h>

#define D_MODEL 1024
#define N_HEAD  16
#define D_K     64
#define BATCH   2
#define SEQ     2048
#define MROWS   (BATCH * SEQ)   // 4096
#define WELEM   (D_MODEL * D_MODEL)
#define XELEM   (MROWS * D_MODEL)

// ===================== scratch (allocation-free: device globals) ============
__device__ __nv_bfloat16 g_W4hi[4 * WELEM];   // 4 transposed-split weights
__device__ __nv_bfloat16 g_W4lo[4 * WELEM];
__device__ __nv_bfloat16 g_X3hi[3 * XELEM];   // split q,k,v inputs
__device__ __nv_bfloat16 g_X3lo[3 * XELEM];
__device__ __nv_bfloat16 g_Qhi[XELEM], g_Qlo[XELEM];
__device__ __nv_bfloat16 g_Khi[XELEM], g_Klo[XELEM];
__device__ __nv_bfloat16 g_Vhi[XELEM], g_Vlo[XELEM];
__device__ __nv_bfloat16 g_Ahi[XELEM], g_Alo[XELEM];   // attention output (split)

// ===================== helpers ==============================================
__device__ __forceinline__ uint32_t smem_u32_of(const void* p) {
    uint32_t a;
    asm("{ .reg .u64 t; cvta.to.shared.u64 t, %1; cvt.u32.u64 %0, t; }"
        : "=r"(a) : "l"(p));
    return a;
}
__device__ __forceinline__ void ldmx4(uint32_t addr, uint32_t& r0, uint32_t& r1,
                                      uint32_t& r2, uint32_t& r3) {
    asm volatile("ldmatrix.sync.aligned.m8n8.x4.shared.b16 {%0,%1,%2,%3}, [%4];"
                 : "=r"(r0), "=r"(r1), "=r"(r2), "=r"(r3) : "r"(addr));
}
__device__ __forceinline__ void ldmx4t(uint32_t addr, uint32_t& r0, uint32_t& r1,
                                       uint32_t& r2, uint32_t& r3) {
    asm volatile("ldmatrix.sync.aligned.m8n8.x4.trans.shared.b16 {%0,%1,%2,%3}, [%4];"
                 : "=r"(r0), "=r"(r1), "=r"(r2), "=r"(r3) : "r"(addr));
}
__device__ __forceinline__ void mma16816(float* c, const uint32_t* a,
                                         uint32_t b0, uint32_t b1) {
    asm volatile(
        "mma.sync.aligned.m16n8k16.row.col.f32.bf16.bf16.f32 "
        "{%0,%1,%2,%3}, {%4,%5,%6,%7}, {%8,%9}, {%0,%1,%2,%3};"
        : "+f"(c[0]), "+f"(c[1]), "+f"(c[2]), "+f"(c[3])
        : "r"(a[0]), "r"(a[1]), "r"(a[2]), "r"(a[3]), "r"(b0), "r"(b1));
}
__device__ __forceinline__ uint32_t pack_bf16(float x, float y) {
    __nv_bfloat162 t = __floats2bfloat162_rn(x, y);
    return *(uint32_t*)&t;
}
__device__ __forceinline__ void cp16(uint32_t dst, const void* src) {
    asm volatile("cp.async.cg.shared.global [%0], [%1], 16;"
                 :: "r"(dst), "l"(src) : "memory");
}
#define CP_COMMIT()  asm volatile("cp.async.commit_group;" ::: "memory")
#define CP_WAIT1()   asm volatile("cp.async.wait_group 1;" ::: "memory")

// ===================== fused conversions ====================================
__global__ __launch_bounds__(256) void split_all(
    const float* __restrict__ x0, const float* __restrict__ x1,
    const float* __restrict__ x2)
{
    const int which = blockIdx.y;
    const float* x = (which == 0) ? x0 : (which == 1) ? x1 : x2;
    __nv_bfloat16* hi = g_X3hi + (size_t)which * XELEM;
    __nv_bfloat16* lo = g_X3lo + (size_t)which * XELEM;
    const int i = blockIdx.x * 256 + threadIdx.x;
    float4 v = ((const float4*)x)[i];
    __nv_bfloat16 h0 = __float2bfloat16_rn(v.x);
    __nv_bfloat16 h1 = __float2bfloat16_rn(v.y);
    __nv_bfloat16 h2 = __float2bfloat16_rn(v.z);
    __nv_bfloat16 h3 = __float2bfloat16_rn(v.w);
    ((__nv_bfloat162*)hi)[i * 2 + 0] = __nv_bfloat162(h0, h1);
    ((__nv_bfloat162*)hi)[i * 2 + 1] = __nv_bfloat162(h2, h3);
    ((__nv_bfloat162*)lo)[i * 2 + 0] = __nv_bfloat162(
        __float2bfloat16_rn(v.x - __bfloat162float(h0)),
        __float2bfloat16_rn(v.y - __bfloat162float(h1)));
    ((__nv_bfloat162*)lo)[i * 2 + 1] = __nv_bfloat162(
        __float2bfloat16_rn(v.z - __bfloat162float(h2)),
        __float2bfloat16_rn(v.w - __bfloat162float(h3)));
}

__global__ __launch_bounds__(256) void wsplit_all(
    const float* __restrict__ w0, const float* __restrict__ w1,
    const float* __restrict__ w2, const float* __restrict__ w3)
{
    __shared__ float t[32][33];
    const int z = blockIdx.z;
    const float* W = (z == 0) ? w0 : (z == 1) ? w1 : (z == 2) ? w2 : w3;
    __nv_bfloat16* hiT = g_W4hi + (size_t)z * WELEM;
    __nv_bfloat16* loT = g_W4lo + (size_t)z * WELEM;
    const int nBase = blockIdx.x * 32, kBase = blockIdx.y * 32;
    const int tx = threadIdx.x, ty = threadIdx.y;
    #pragma unroll
    for (int r = 0; r < 4; r++)
        t[ty + 8 * r][tx] = W[(size_t)(kBase + ty + 8 * r) * D_MODEL + nBase + tx];
    __syncthreads();
    #pragma unroll
    for (int r = 0; r < 4; r++) {
        float v = t[tx][ty + 8 * r];
        __nv_bfloat16 h = __float2bfloat16_rn(v);
        size_t o = (size_t)(nBase + ty + 8 * r) * D_MODEL + kBase + tx;
        hiT[o] = h;
        loT[o] = __float2bfloat16_rn(v - __bfloat162float(h));
    }
}

// ===================== HMMA split-bf16 GEMM core ============================
// XOR-swizzled smem: combined (hi|lo) tiles, 128 rows x 128B,
// phys chunk = logical_chunk ^ (row & 7).  3-stage cp.async, 1 sync/chunk.
#define GBM 128
#define GBN 128
#define GBK 32
#define G_TILE_B 16384                 // one combined tile: 128 rows * 128 B
#define G_STG_B  (2 * G_TILE_B)        // A-combined + B-combined = 32768
#define G_SMEM   (3 * G_STG_B)         // 98304
#define NCH (D_MODEL / GBK)            // 32

__device__ __forceinline__ void gemm_core(
    const __nv_bfloat16* __restrict__ Ahi, const __nv_bfloat16* __restrict__ Alo,
    const __nv_bfloat16* __restrict__ Bhi, const __nv_bfloat16* __restrict__ Blo,
    const float* __restrict__ bias, float* __restrict__ C,
    __nv_bfloat16* __restrict__ Chi, __nv_bfloat16* __restrict__ Clo,
    float scale, char* smem)
{
    const uint32_t dsb = smem_u32_of(smem);
    const int tid = threadIdx.x;
    const int wid = tid >> 5;
    const int lane = tid & 31;
    const int warp_m = wid & 1;
    const int warp_n = wid >> 1;
    const size_t rBase = (size_t)blockIdx.y * GBM;
    const size_t nBase = (size_t)blockIdx.x * GBN;

    float acc[4][4][4] = {};

    // loader geometry: thread covers rows (tid>>2, +64), chunk tid&3 (hi) and +4 (lo)
    const int lr = tid >> 2;
    const int lc = tid & 3;
    const int gcol = lc * 8;

    auto issue = [&](int ck, int stg) {
        const uint32_t sb = dsb + (uint32_t)(stg * G_STG_B);
        const int k0 = ck * GBK;
        #pragma unroll
        for (int it = 0; it < 2; it++) {
            const int r = lr + it * 64;
            const uint32_t ph = (uint32_t)(((lc ^ (r & 7)) * 16));
            const uint32_t ro = (uint32_t)(r * 128);
            const size_t gA = (rBase + r) * D_MODEL + k0 + gcol;
            const size_t gB = (nBase + r) * D_MODEL + k0 + gcol;
            cp16(sb + ro + ph, Ahi + gA);
            cp16(sb + ro + (ph ^ 64), Alo + gA);
            cp16(sb + G_TILE_B + ro + ph, Bhi + gB);
            cp16(sb + G_TILE_B + ro + (ph ^ 64), Blo + gB);
        }
    };

    issue(0, 0); CP_COMMIT();
    issue(1, 1); CP_COMMIT();

    // fragment base addresses (stage 0, kk=0, hi): logical chunk = lane>>4
    const int lrow = lane & 15;
    const uint32_t phys0 = (uint32_t)((((lane >> 4) ^ (lane & 7)) * 16));
    uint32_t aB[4], bB[2];
    #pragma unroll
    for (int mi = 0; mi < 4; mi++)
        aB[mi] = dsb + (uint32_t)((warp_m * 64 + mi * 16 + lrow) * 128) + phys0;
    #pragma unroll
    for (int p = 0; p < 2; p++)
        bB[p] = dsb + G_TILE_B + (uint32_t)((warp_n * 32 + p * 16 + lrow) * 128) + phys0;

    int sC = 0, sI = 2;     // compute stage, issue stage
    for (int c = 0; c < NCH; c++) {
        CP_WAIT1();
        __syncthreads();
        if (c + 2 < NCH) issue(c + 2, sI);
        CP_COMMIT();                       // empty group in the tail is fine
        sI = (sI == 2) ? 0 : sI + 1;

        const uint32_t so = (uint32_t)(sC * G_STG_B);
        sC = (sC == 2) ? 0 : sC + 1;

        #pragma unroll
        for (int kk = 0; kk < 2; kk++) {
            const uint32_t xk = (uint32_t)(kk * 32);   // logical chunk +2 -> ^32
            uint32_t bh[8], bl[8];
            #pragma unroll
            for (int p = 0; p < 2; p++) {
                const uint32_t ad = (bB[p] + so) ^ xk;
                uint32_t r0, r1, r2, r3;
                ldmx4(ad, r0, r1, r2, r3);             // hi
                bh[p * 4 + 0] = r0; bh[p * 4 + 1] = r2;
                bh[p * 4 + 2] = r1; bh[p * 4 + 3] = r3;
                ldmx4(ad ^ 64, r0, r1, r2, r3);        // lo (logical +4 -> ^64)
                bl[p * 4 + 0] = r0; bl[p * 4 + 1] = r2;
                bl[p * 4 + 2] = r1; bl[p * 4 + 3] = r3;
            }
            #pragma unroll
            for (int mi = 0; mi < 4; mi++) {
                const uint32_t aa = (aB[mi] + so) ^ xk;
                uint32_t ah[4], al[4];
                ldmx4(aa, ah[0], ah[1], ah[2], ah[3]);
                ldmx4(aa ^ 64, al[0], al[1], al[2], al[3]);
                #pragma unroll
                for (int ni = 0; ni < 4; ni++) {
                    const uint32_t b0h = bh[(ni >> 1) * 4 + (ni & 1) * 2];
                    const uint32_t b1h = bh[(ni >> 1) * 4 + (ni & 1) * 2 + 1];
                    const uint32_t b0l = bl[(ni >> 1) * 4 + (ni & 1) * 2];
                    const uint32_t b1l = bl[(ni >> 1) * 4 + (ni & 1) * 2 + 1];
                    mma16816(acc[mi][ni], ah, b0h, b1h);
                    mma16816(acc[mi][ni], ah, b0l, b1l);
                    mma16816(acc[mi][ni], al, b0h, b1h);
                }
            }
        }
    }

    // ---- epilogue ----
    const int crow = lane >> 2;
    const int ccol = (lane & 3) * 2;
    #pragma unroll
    for (int mi = 0; mi < 4; mi++) {
        #pragma unroll
        for (int ni = 0; ni < 4; ni++) {
            const size_t row0 = rBase + warp_m * 64 + mi * 16 + crow;
            const size_t col = nBase + warp_n * 32 + ni * 8 + ccol;
            const float b0 = bias[col], b1 = bias[col + 1];
            float v00 = acc[mi][ni][0] + b0, v01 = acc[mi][ni][1] + b1;
            float v10 = acc[mi][ni][2] + b0, v11 = acc[mi][ni][3] + b1;
            if (Chi) {
                v00 *= scale; v01 *= scale; v10 *= scale; v11 *= scale;
                __nv_bfloat16 h00 = __float2bfloat16_rn(v00);
                __nv_bfloat16 h01 = __float2bfloat16_rn(v01);
                __nv_bfloat16 h10 = __float2bfloat16_rn(v10);
                __nv_bfloat16 h11 = __float2bfloat16_rn(v11);
                *(__nv_bfloat162*)(Chi + row0 * D_MODEL + col) = __nv_bfloat162(h00, h01);
                *(__nv_bfloat162*)(Chi + (row0 + 8) * D_MODEL + col) = __nv_bfloat162(h10, h11);
                *(__nv_bfloat162*)(Clo + row0 * D_MODEL + col) = __nv_bfloat162(
                    __float2bfloat16_rn(v00 - __bfloat162float(h00)),
                    __float2bfloat16_rn(v01 - __bfloat162float(h01)));
                *(__nv_bfloat162*)(Clo + (row0 + 8) * D_MODEL + col) = __nv_bfloat162(
                    __float2bfloat16_rn(v10 - __bfloat162float(h10)),
                    __float2bfloat16_rn(v11 - __bfloat162float(h11)));
            } else {
                *(float2*)(C + row0 * D_MODEL + col) = make_float2(v00, v01);
                *(float2*)(C + (row0 + 8) * D_MODEL + col) = make_float2(v10, v11);
            }
        }
    }
}

// QKV projections fused into one launch (blockIdx.z selects)
__global__ __launch_bounds__(256, 2) void gemm_qkv(
    const float* __restrict__ b_q, const float* __restrict__ b_k,
    const float* __restrict__ b_v)
{
    extern __shared__ __align__(128) char smem_q[];
    const int z = blockIdx.z;
    const __nv_bfloat16* Ahi = g_X3hi + (size_t)z * XELEM;
    const __nv_bfloat16* Alo = g_X3lo + (size_t)z * XELEM;
    const __nv_bfloat16* Bhi = g_W4hi + (size_t)z * WELEM;
    const __nv_bfloat16* Blo = g_W4lo + (size_t)z * WELEM;
    const float* bias = (z == 0) ? b_q : (z == 1) ? b_k : b_v;
    __nv_bfloat16* Chi = (z == 0) ? g_Qhi : (z == 1) ? g_Khi : g_Vhi;
    __nv_bfloat16* Clo = (z == 0) ? g_Qlo : (z == 1) ? g_Klo : g_Vlo;
    const float scale = (z == 0) ? 0.125f : 1.0f;
    gemm_core(Ahi, Alo, Bhi, Blo, bias, nullptr, Chi, Clo, scale, smem_q);
}

__global__ __launch_bounds__(256, 2) void gemm_o(
    const float* __restrict__ b_o, float* __restrict__ out)
{
    extern __shared__ __align__(128) char smem_o[];
    gemm_core(g_Ahi, g_Alo, g_W4hi + 3 * (size_t)WELEM, g_W4lo + 3 * (size_t)WELEM,
              b_o, out, nullptr, nullptr, 1.0f, smem_o);
}

// ===================== tensor-core flash attention (3-stage, 1 sync/iter) ===
#define AKT 64
#define ASTR 72
#define AT_TILE (AKT * ASTR)               // 4608 elems
#define AT_STG_B (4 * AT_TILE * 2)         // 36864 bytes (Kh,Kl,Vh,Vl)
#define ATTN_SMEM (3 * AT_STG_B)           // 110592
#define NKT (SEQ / AKT)                    // 32

__global__ __launch_bounds__(256, 1) void attn_mma()
{
    extern __shared__ __align__(128) __nv_bfloat16 as_[];
    const uint32_t asb = smem_u32_of(as_);

    const int qt = blockIdx.x;
    const int hb = blockIdx.y;
    const int h = hb / BATCH;
    const int b = hb % BATCH;
    const int tid = threadIdx.x;
    const int wid = tid >> 5;
    const int lane = tid & 31;

    const size_t headOff = (size_t)b * SEQ * D_MODEL + (size_t)h * D_K;
    const __nv_bfloat16* Qh = g_Qhi + headOff;
    const __nv_bfloat16* Ql = g_Qlo + headOff;
    const __nv_bfloat16* Kh = g_Khi + headOff;
    const __nv_bfloat16* Kl = g_Klo + headOff;
    const __nv_bfloat16* Vh = g_Vhi + headOff;
    const __nv_bfloat16* Vl = g_Vlo + headOff;

    // K/V stage loader
    const int ldr = tid >> 2;
    const int ldc = (tid & 3) * 8;
    auto kvissue = [&](int kt, int stg) {
        const uint32_t sb = asb + (uint32_t)(stg * AT_STG_B);
        #pragma unroll
        for (int it = 0; it < 2; it++) {
            const int c8 = ldc + it * 32;
            const size_t g = (size_t)(kt * AKT + ldr) * D_MODEL + c8;
            const uint32_t so = (uint32_t)((ldr * ASTR + c8) * 2);
            cp16(sb + 0 * AT_TILE * 2 + so, Kh + g);
            cp16(sb + 1 * AT_TILE * 2 + so, Kl + g);
            cp16(sb + 2 * AT_TILE * 2 + so, Vh + g);
            cp16(sb + 3 * AT_TILE * 2 + so, Vl + g);
        }
    };

    // prefetch kt 0,1 into stages 0,1 while we stage Q in stage 2
    kvissue(0, 0); CP_COMMIT();
    kvissue(1, 1); CP_COMMIT();

    // ---- stage Q (128x64 hi+lo) into stage-2 tile slots ----
    __nv_bfloat16* q2 = as_ + 2 * (4 * AT_TILE);
    #pragma unroll
    for (int i = 0; i < 4; i++) {
        const int u = tid + i * 256;
        const int r = u >> 3, c8 = (u & 7) * 8;
        const size_t g = (size_t)(qt * 128 + r) * D_MODEL + c8;
        const int slotH = (r < 64) ? 0 : 1;
        const int slotL = (r < 64) ? 2 : 3;
        const int rr = r & 63;
        *(uint4*)(q2 + slotH * AT_TILE + rr * ASTR + c8) = *(const uint4*)(Qh + g);
        *(uint4*)(q2 + slotL * AT_TILE + rr * ASTR + c8) = *(const uint4*)(Ql + g);
    }
    __syncthreads();

    uint32_t qh[4][4], ql[4][4];
    {
        const int rb = (wid & 3) * 16 + (lane & 15);
        const uint32_t offB = (uint32_t)((lane >> 4) * 16 + rb * ASTR * 2);
        const uint32_t s2 = asb + 2 * AT_STG_B;
        const uint32_t aH = s2 + ((wid < 4) ? 0 : AT_TILE * 2) + offB;
        const uint32_t aL = s2 + ((wid < 4) ? 2 * AT_TILE * 2 : 3 * AT_TILE * 2) + offB;
        #pragma unroll
        for (int kt = 0; kt < 4; kt++) {
            ldmx4(aH + kt * 32, qh[kt][0], qh[kt][1], qh[kt][2], qh[kt][3]);
            ldmx4(aL + kt * 32, ql[kt][0], ql[kt][1], ql[kt][2], ql[kt][3]);
        }
    }
    // no extra sync: the first loop iteration's sync orders Q reads before
    // cp.async overwrites stage 2 (issued only after that sync).

    float m0 = -1e30f, m1 = -1e30f, l0 = 0.0f, l1 = 0.0f;
    float o[8][4] = {};

    // stage-0 fragment bases
    const uint32_t lof = (uint32_t)(((lane & 15) * ASTR + (lane >> 4) * 8) * 2);
    const uint32_t kB0 = asb + lof;
    const uint32_t kL0 = kB0 + AT_TILE * 2;
    const uint32_t vB0 = kB0 + 2 * AT_TILE * 2;
    const uint32_t vL0 = kB0 + 3 * AT_TILE * 2;

    int sC = 0, sI = 2;
    for (int kt0 = 0; kt0 < NKT; kt0++) {
        CP_WAIT1();
        __syncthreads();
        if (kt0 + 2 < NKT) kvissue(kt0 + 2, sI);
        CP_COMMIT();
        sI = (sI == 2) ? 0 : sI + 1;
        const uint32_t so = (uint32_t)(sC * AT_STG_B);
        sC = (sC == 2) ? 0 : sC + 1;

        // ---- S = Q K^T (scale pre-folded into Q) ----
        float sc[8][4] = {};
        #pragma unroll
        for (int np = 0; np < 4; np++) {
            #pragma unroll
            for (int kt = 0; kt < 4; kt++) {
                const uint32_t off = (uint32_t)(np * 16 * ASTR * 2 + kt * 32) + so;
                uint32_t h0, h1, h2, h3, x0, x1, x2, x3;
                ldmx4(kB0 + off, h0, h1, h2, h3);
                ldmx4(kL0 + off, x0, x1, x2, x3);
                mma16816(sc[2 * np],     qh[kt], h0, h2);
                mma16816(sc[2 * np],     ql[kt], h0, h2);
                mma16816(sc[2 * np],     qh[kt], x0, x2);
                mma16816(sc[2 * np + 1], qh[kt], h1, h3);
                mma16816(sc[2 * np + 1], ql[kt], h1, h3);
                mma16816(sc[2 * np + 1], qh[kt], x1, x3);
            }
        }

        // ---- online softmax ----
        float mx0 = -1e30f, mx1 = -1e30f;
        #pragma unroll
        for (int nt = 0; nt < 8; nt++) {
            mx0 = fmaxf(mx0, fmaxf(sc[nt][0], sc[nt][1]));
            mx1 = fmaxf(mx1, fmaxf(sc[nt][2], sc[nt][3]));
        }
        mx0 = fmaxf(mx0, __shfl_xor_sync(0xffffffffu, mx0, 1));
        mx0 = fmaxf(mx0, __shfl_xor_sync(0xffffffffu, mx0, 2));
        mx1 = fmaxf(mx1, __shfl_xor_sync(0xffffffffu, mx1, 1));
        mx1 = fmaxf(mx1, __shfl_xor_sync(0xffffffffu, mx1, 2));
        const float m0n = fmaxf(m0, mx0), m1n = fmaxf(m1, mx1);
        const float a0 = __expf(m0 - m0n), a1 = __expf(m1 - m1n);
        float rs0 = 0.0f, rs1 = 0.0f;
        #pragma unroll
        for (int nt = 0; nt < 8; nt++) {
            sc[nt][0] = __expf(sc[nt][0] - m0n);
            sc[nt][1] = __expf(sc[nt][1] - m0n);
            sc[nt][2] = __expf(sc[nt][2] - m1n);
            sc[nt][3] = __expf(sc[nt][3] - m1n);
            rs0 += sc[nt][0] + sc[nt][1];
            rs1 += sc[nt][2] + sc[nt][3];
            o[nt][0] *= a0; o[nt][1] *= a0;
            o[nt][2] *= a1; o[nt][3] *= a1;
        }
        rs0 += __shfl_xor_sync(0xffffffffu, rs0, 1);
        rs0 += __shfl_xor_sync(0xffffffffu, rs0, 2);
        rs1 += __shfl_xor_sync(0xffffffffu, rs1, 1);
        rs1 += __shfl_xor_sync(0xffffffffu, rs1, 2);
        l0 = l0 * a0 + rs0;
        l1 = l1 * a1 + rs1;
        m0 = m0n; m1 = m1n;

        // ---- split P into hi/lo fragments ----
        uint32_t ph[4][4], pl[4][4];
        #pragma unroll
        for (int kt = 0; kt < 4; kt++) {
            const float* sa = sc[2 * kt];
            const float* sb2 = sc[2 * kt + 1];
            float hv;
            float la0, la1, la2, la3, lb0, lb1, lb2, lb3;
            hv = __bfloat162float(__float2bfloat16_rn(sa[0])); la0 = sa[0] - hv;
            hv = __bfloat162float(__float2bfloat16_rn(sa[1])); la1 = sa[1] - hv;
            hv = __bfloat162float(__float2bfloat16_rn(sa[2])); la2 = sa[2] - hv;
            hv = __bfloat162float(__float2bfloat16_rn(sa[3])); la3 = sa[3] - hv;
            hv = __bfloat162float(__float2bfloat16_rn(sb2[0])); lb0 = sb2[0] - hv;
            hv = __bfloat162float(__float2bfloat16_rn(sb2[1])); lb1 = sb2[1] - hv;
            hv = __bfloat162float(__float2bfloat16_rn(sb2[2])); lb2 = sb2[2] - hv;
            hv = __bfloat162float(__float2bfloat16_rn(sb2[3])); lb3 = sb2[3] - hv;
            ph[kt][0] = pack_bf16(sa[0], sa[1]);
            ph[kt][1] = pack_bf16(sa[2], sa[3]);
            ph[kt][2] = pack_bf16(sb2[0], sb2[1]);
            ph[kt][3] = pack_bf16(sb2[2], sb2[3]);
            pl[kt][0] = pack_bf16(la0, la1);
            pl[kt][1] = pack_bf16(la2, la3);
            pl[kt][2] = pack_bf16(lb0, lb1);
            pl[kt][3] = pack_bf16(lb2, lb3);
        }

        // ---- O += P @ V ----
        #pragma unroll
        for (int np = 0; np < 4; np++) {
            #pragma unroll
            for (int kt = 0; kt < 4; kt++) {
                const uint32_t off = (uint32_t)((kt * 16 * ASTR + np * 16) * 2) + so;
                uint32_t h0, h1, h2, h3, x0, x1, x2, x3;
                ldmx4t(vB0 + off, h0, h1, h2, h3);
                ldmx4t(vL0 + off, x0, x1, x2, x3);
                mma16816(o[2 * np],     ph[kt], h0, h1);
                mma16816(o[2 * np],     pl[kt], h0, h1);
                mma16816(o[2 * np],     ph[kt], x0, x1);
                mma16816(o[2 * np + 1], ph[kt], h2, h3);
                mma16816(o[2 * np + 1], pl[kt], h2, h3);
                mma16816(o[2 * np + 1], ph[kt], x2, x3);
            }
        }
    }

    // ---- epilogue ----
    const float inv0 = 1.0f / l0, inv1 = 1.0f / l1;
    const size_t row0 = (size_t)b * SEQ + qt * 128 + wid * 16 + (lane >> 2);
    const size_t row1 = row0 + 8;
    const int colB = h * D_K + (lane & 3) * 2;
    #pragma unroll
    for (int nt = 0; nt < 8; nt++) {
        const size_t c = colB + nt * 8;
        float v00 = o[nt][0] * inv0, v01 = o[nt][1] * inv0;
        float v10 = o[nt][2] * inv1, v11 = o[nt][3] * inv1;
        __nv_bfloat16 h00 = __float2bfloat16_rn(v00);
        __nv_bfloat16 h01 = __float2bfloat16_rn(v01);
        __nv_bfloat16 h10 = __float2bfloat16_rn(v10);
        __nv_bfloat16 h11 = __float2bfloat16_rn(v11);
        *(__nv_bfloat162*)(g_Ahi + row0 * D_MODEL + c) = __nv_bfloat162(h00, h01);
        *(__nv_bfloat162*)(g_Ahi + row1 * D_MODEL + c) = __nv_bfloat162(h10, h11);
        *(__nv_bfloat162*)(g_Alo + row0 * D_MODEL + c) = __nv_bfloat162(
            __float2bfloat16_rn(v00 - __bfloat162float(h00)),
            __float2bfloat16_rn(v01 - __bfloat162float(h01)));
        *(__nv_bfloat162*)(g_Alo + row1 * D_MODEL + c) = __nv_bfloat162(
            __float2bfloat16_rn(v10 - __bfloat162float(h10)),
            __float2bfloat16_rn(v11 - __bfloat162float(h11)));
    }
}

// ===================== launch ==============================================
extern "C" void kernel_launch(void* const* d_in, const int* in_sizes, int n_in,
                              void* d_out, int out_size)
{
    const float* q   = (const float*)d_in[0];
    const float* k   = (const float*)d_in[1];
    const float* v   = (const float*)d_in[2];
    const float* w_q = (const float*)d_in[3];
    const float* b_q = (const float*)d_in[4];
    const float* w_k = (const float*)d_in[5];
    const float* b_k = (const float*)d_in[6];
    const float* w_v = (const float*)d_in[7];
    const float* b_v = (const float*)d_in[8];
    const float* w_o = (const float*)d_in[9];
    const float* b_o = (const float*)d_in[10];
    float* out = (float*)d_out;

    cudaFuncSetAttribute(gemm_qkv, cudaFuncAttributeMaxDynamicSharedMemorySize, G_SMEM);
    cudaFuncSetAttribute(gemm_o,   cudaFuncAttributeMaxDynamicSharedMemorySize, G_SMEM);
    cudaFuncSetAttribute(attn_mma, cudaFuncAttributeMaxDynamicSharedMemorySize, ATTN_SMEM);

    const int n4 = XELEM / 4;

    // conversions (fused)
    wsplit_all<<<dim3(32, 32, 4), dim3(32, 8)>>>(w_q, w_k, w_v, w_o);
    split_all<<<dim3(n4 / 256, 3), 256>>>(q, k, v);

    // Q/K/V projections in one launch
    gemm_qkv<<<dim3(D_MODEL / GBN, MROWS / GBM, 3), 256, G_SMEM>>>(b_q, b_k, b_v);

    // attention
    attn_mma<<<dim3(SEQ / 128, N_HEAD * BATCH), 256, ATTN_SMEM>>>();

    // output projection
    gemm_o<<<dim3(D_MODEL / GBN, MROWS / GBM), 256, G_SMEM>>>(b_o, out);
}

// round 7
// speedup vs baseline: 2.8229x; 1.0462x over previous
#include <cuda_runtime.h>
#include <cuda_bf16.h>
#include <cstdint>
#include <math.h>

#define D_MODEL 1024
#define N_HEAD  16
#define D_K     64
#define BATCH   2
#define SEQ     2048
#define MROWS   (BATCH * SEQ)   // 4096
#define WELEM   (D_MODEL * D_MODEL)
#define XELEM   (MROWS * D_MODEL)

// ===================== scratch (allocation-free: device globals) ============
__device__ __nv_bfloat16 g_W4hi[4 * WELEM];   // 4 transposed-split weights
__device__ __nv_bfloat16 g_W4lo[4 * WELEM];
__device__ __nv_bfloat16 g_X3hi[3 * XELEM];   // split q,k,v inputs
__device__ __nv_bfloat16 g_X3lo[3 * XELEM];
__device__ __nv_bfloat16 g_Qhi[XELEM], g_Qlo[XELEM];
__device__ __nv_bfloat16 g_Khi[XELEM], g_Klo[XELEM];
__device__ __nv_bfloat16 g_Vhi[XELEM], g_Vlo[XELEM];
__device__ __nv_bfloat16 g_Ahi[XELEM], g_Alo[XELEM];   // attention output (split)

// ===================== helpers ==============================================
__device__ __forceinline__ uint32_t smem_u32_of(const void* p) {
    uint32_t a;
    asm("{ .reg .u64 t; cvta.to.shared.u64 t, %1; cvt.u32.u64 %0, t; }"
        : "=r"(a) : "l"(p));
    return a;
}
__device__ __forceinline__ void ldmx4(uint32_t addr, uint32_t& r0, uint32_t& r1,
                                      uint32_t& r2, uint32_t& r3) {
    asm volatile("ldmatrix.sync.aligned.m8n8.x4.shared.b16 {%0,%1,%2,%3}, [%4];"
                 : "=r"(r0), "=r"(r1), "=r"(r2), "=r"(r3) : "r"(addr));
}
__device__ __forceinline__ void ldmx4t(uint32_t addr, uint32_t& r0, uint32_t& r1,
                                       uint32_t& r2, uint32_t& r3) {
    asm volatile("ldmatrix.sync.aligned.m8n8.x4.trans.shared.b16 {%0,%1,%2,%3}, [%4];"
                 : "=r"(r0), "=r"(r1), "=r"(r2), "=r"(r3) : "r"(addr));
}
__device__ __forceinline__ void mma16816(float* c, const uint32_t* a,
                                         uint32_t b0, uint32_t b1) {
    asm volatile(
        "mma.sync.aligned.m16n8k16.row.col.f32.bf16.bf16.f32 "
        "{%0,%1,%2,%3}, {%4,%5,%6,%7}, {%8,%9}, {%0,%1,%2,%3};"
        : "+f"(c[0]), "+f"(c[1]), "+f"(c[2]), "+f"(c[3])
        : "r"(a[0]), "r"(a[1]), "r"(a[2]), "r"(a[3]), "r"(b0), "r"(b1));
}
__device__ __forceinline__ uint32_t pack_bf16(float x, float y) {
    __nv_bfloat162 t = __floats2bfloat162_rn(x, y);
    return *(uint32_t*)&t;
}
__device__ __forceinline__ void cp16(uint32_t dst, const void* src) {
    asm volatile("cp.async.cg.shared.global [%0], [%1], 16;"
                 :: "r"(dst), "l"(src) : "memory");
}
#define CP_COMMIT()  asm volatile("cp.async.commit_group;" ::: "memory")
#define CP_WAIT1()   asm volatile("cp.async.wait_group 1;" ::: "memory")

// ===================== fused conversions ====================================
__global__ __launch_bounds__(256) void split_all(
    const float* __restrict__ x0, const float* __restrict__ x1,
    const float* __restrict__ x2)
{
    const int which = blockIdx.y;
    const float* x = (which == 0) ? x0 : (which == 1) ? x1 : x2;
    __nv_bfloat16* hi = g_X3hi + (size_t)which * XELEM;
    __nv_bfloat16* lo = g_X3lo + (size_t)which * XELEM;
    const int i = blockIdx.x * 256 + threadIdx.x;
    float4 v = ((const float4*)x)[i];
    __nv_bfloat16 h0 = __float2bfloat16_rn(v.x);
    __nv_bfloat16 h1 = __float2bfloat16_rn(v.y);
    __nv_bfloat16 h2 = __float2bfloat16_rn(v.z);
    __nv_bfloat16 h3 = __float2bfloat16_rn(v.w);
    ((__nv_bfloat162*)hi)[i * 2 + 0] = __nv_bfloat162(h0, h1);
    ((__nv_bfloat162*)hi)[i * 2 + 1] = __nv_bfloat162(h2, h3);
    ((__nv_bfloat162*)lo)[i * 2 + 0] = __nv_bfloat162(
        __float2bfloat16_rn(v.x - __bfloat162float(h0)),
        __float2bfloat16_rn(v.y - __bfloat162float(h1)));
    ((__nv_bfloat162*)lo)[i * 2 + 1] = __nv_bfloat162(
        __float2bfloat16_rn(v.z - __bfloat162float(h2)),
        __float2bfloat16_rn(v.w - __bfloat162float(h3)));
}

__global__ __launch_bounds__(256) void wsplit_all(
    const float* __restrict__ w0, const float* __restrict__ w1,
    const float* __restrict__ w2, const float* __restrict__ w3)
{
    __shared__ float t[32][33];
    const int z = blockIdx.z;
    const float* W = (z == 0) ? w0 : (z == 1) ? w1 : (z == 2) ? w2 : w3;
    __nv_bfloat16* hiT = g_W4hi + (size_t)z * WELEM;
    __nv_bfloat16* loT = g_W4lo + (size_t)z * WELEM;
    const int nBase = blockIdx.x * 32, kBase = blockIdx.y * 32;
    const int tx = threadIdx.x, ty = threadIdx.y;
    #pragma unroll
    for (int r = 0; r < 4; r++)
        t[ty + 8 * r][tx] = W[(size_t)(kBase + ty + 8 * r) * D_MODEL + nBase + tx];
    __syncthreads();
    #pragma unroll
    for (int r = 0; r < 4; r++) {
        float v = t[tx][ty + 8 * r];
        __nv_bfloat16 h = __float2bfloat16_rn(v);
        size_t o = (size_t)(nBase + ty + 8 * r) * D_MODEL + kBase + tx;
        hiT[o] = h;
        loT[o] = __float2bfloat16_rn(v - __bfloat162float(h));
    }
}

// ===================== HMMA split-bf16 GEMM core (unchanged from R6) ========
#define GBM 128
#define GBN 128
#define GBK 32
#define G_TILE_B 16384
#define G_STG_B  (2 * G_TILE_B)
#define G_SMEM   (3 * G_STG_B)
#define NCH (D_MODEL / GBK)

__device__ __forceinline__ void gemm_core(
    const __nv_bfloat16* __restrict__ Ahi, const __nv_bfloat16* __restrict__ Alo,
    const __nv_bfloat16* __restrict__ Bhi, const __nv_bfloat16* __restrict__ Blo,
    const float* __restrict__ bias, float* __restrict__ C,
    __nv_bfloat16* __restrict__ Chi, __nv_bfloat16* __restrict__ Clo,
    float scale, char* smem)
{
    const uint32_t dsb = smem_u32_of(smem);
    const int tid = threadIdx.x;
    const int wid = tid >> 5;
    const int lane = tid & 31;
    const int warp_m = wid & 1;
    const int warp_n = wid >> 1;
    const size_t rBase = (size_t)blockIdx.y * GBM;
    const size_t nBase = (size_t)blockIdx.x * GBN;

    float acc[4][4][4] = {};

    const int lr = tid >> 2;
    const int lc = tid & 3;
    const int gcol = lc * 8;

    auto issue = [&](int ck, int stg) {
        const uint32_t sb = dsb + (uint32_t)(stg * G_STG_B);
        const int k0 = ck * GBK;
        #pragma unroll
        for (int it = 0; it < 2; it++) {
            const int r = lr + it * 64;
            const uint32_t ph = (uint32_t)(((lc ^ (r & 7)) * 16));
            const uint32_t ro = (uint32_t)(r * 128);
            const size_t gA = (rBase + r) * D_MODEL + k0 + gcol;
            const size_t gB = (nBase + r) * D_MODEL + k0 + gcol;
            cp16(sb + ro + ph, Ahi + gA);
            cp16(sb + ro + (ph ^ 64), Alo + gA);
            cp16(sb + G_TILE_B + ro + ph, Bhi + gB);
            cp16(sb + G_TILE_B + ro + (ph ^ 64), Blo + gB);
        }
    };

    issue(0, 0); CP_COMMIT();
    issue(1, 1); CP_COMMIT();

    const int lrow = lane & 15;
    const uint32_t phys0 = (uint32_t)((((lane >> 4) ^ (lane & 7)) * 16));
    uint32_t aB[4], bB[2];
    #pragma unroll
    for (int mi = 0; mi < 4; mi++)
        aB[mi] = dsb + (uint32_t)((warp_m * 64 + mi * 16 + lrow) * 128) + phys0;
    #pragma unroll
    for (int p = 0; p < 2; p++)
        bB[p] = dsb + G_TILE_B + (uint32_t)((warp_n * 32 + p * 16 + lrow) * 128) + phys0;

    int sC = 0, sI = 2;
    for (int c = 0; c < NCH; c++) {
        CP_WAIT1();
        __syncthreads();
        if (c + 2 < NCH) issue(c + 2, sI);
        CP_COMMIT();
        sI = (sI == 2) ? 0 : sI + 1;

        const uint32_t so = (uint32_t)(sC * G_STG_B);
        sC = (sC == 2) ? 0 : sC + 1;

        #pragma unroll
        for (int kk = 0; kk < 2; kk++) {
            const uint32_t xk = (uint32_t)(kk * 32);
            uint32_t bh[8], bl[8];
            #pragma unroll
            for (int p = 0; p < 2; p++) {
                const uint32_t ad = (bB[p] + so) ^ xk;
                uint32_t r0, r1, r2, r3;
                ldmx4(ad, r0, r1, r2, r3);
                bh[p * 4 + 0] = r0; bh[p * 4 + 1] = r2;
                bh[p * 4 + 2] = r1; bh[p * 4 + 3] = r3;
                ldmx4(ad ^ 64, r0, r1, r2, r3);
                bl[p * 4 + 0] = r0; bl[p * 4 + 1] = r2;
                bl[p * 4 + 2] = r1; bl[p * 4 + 3] = r3;
            }
            #pragma unroll
            for (int mi = 0; mi < 4; mi++) {
                const uint32_t aa = (aB[mi] + so) ^ xk;
                uint32_t ah[4], al[4];
                ldmx4(aa, ah[0], ah[1], ah[2], ah[3]);
                ldmx4(aa ^ 64, al[0], al[1], al[2], al[3]);
                #pragma unroll
                for (int ni = 0; ni < 4; ni++) {
                    const uint32_t b0h = bh[(ni >> 1) * 4 + (ni & 1) * 2];
                    const uint32_t b1h = bh[(ni >> 1) * 4 + (ni & 1) * 2 + 1];
                    const uint32_t b0l = bl[(ni >> 1) * 4 + (ni & 1) * 2];
                    const uint32_t b1l = bl[(ni >> 1) * 4 + (ni & 1) * 2 + 1];
                    mma16816(acc[mi][ni], ah, b0h, b1h);
                    mma16816(acc[mi][ni], ah, b0l, b1l);
                    mma16816(acc[mi][ni], al, b0h, b1h);
                }
            }
        }
    }

    const int crow = lane >> 2;
    const int ccol = (lane & 3) * 2;
    #pragma unroll
    for (int mi = 0; mi < 4; mi++) {
        #pragma unroll
        for (int ni = 0; ni < 4; ni++) {
            const size_t row0 = rBase + warp_m * 64 + mi * 16 + crow;
            const size_t col = nBase + warp_n * 32 + ni * 8 + ccol;
            const float b0 = bias[col], b1 = bias[col + 1];
            float v00 = acc[mi][ni][0] + b0, v01 = acc[mi][ni][1] + b1;
            float v10 = acc[mi][ni][2] + b0, v11 = acc[mi][ni][3] + b1;
            if (Chi) {
                v00 *= scale; v01 *= scale; v10 *= scale; v11 *= scale;
                __nv_bfloat16 h00 = __float2bfloat16_rn(v00);
                __nv_bfloat16 h01 = __float2bfloat16_rn(v01);
                __nv_bfloat16 h10 = __float2bfloat16_rn(v10);
                __nv_bfloat16 h11 = __float2bfloat16_rn(v11);
                *(__nv_bfloat162*)(Chi + row0 * D_MODEL + col) = __nv_bfloat162(h00, h01);
                *(__nv_bfloat162*)(Chi + (row0 + 8) * D_MODEL + col) = __nv_bfloat162(h10, h11);
                *(__nv_bfloat162*)(Clo + row0 * D_MODEL + col) = __nv_bfloat162(
                    __float2bfloat16_rn(v00 - __bfloat162float(h00)),
                    __float2bfloat16_rn(v01 - __bfloat162float(h01)));
                *(__nv_bfloat162*)(Clo + (row0 + 8) * D_MODEL + col) = __nv_bfloat162(
                    __float2bfloat16_rn(v10 - __bfloat162float(h10)),
                    __float2bfloat16_rn(v11 - __bfloat162float(h11)));
            } else {
                *(float2*)(C + row0 * D_MODEL + col) = make_float2(v00, v01);
                *(float2*)(C + (row0 + 8) * D_MODEL + col) = make_float2(v10, v11);
            }
        }
    }
}

__global__ __launch_bounds__(256, 2) void gemm_qkv(
    const float* __restrict__ b_q, const float* __restrict__ b_k,
    const float* __restrict__ b_v)
{
    extern __shared__ __align__(128) char smem_q[];
    const int z = blockIdx.z;
    const __nv_bfloat16* Ahi = g_X3hi + (size_t)z * XELEM;
    const __nv_bfloat16* Alo = g_X3lo + (size_t)z * XELEM;
    const __nv_bfloat16* Bhi = g_W4hi + (size_t)z * WELEM;
    const __nv_bfloat16* Blo = g_W4lo + (size_t)z * WELEM;
    const float* bias = (z == 0) ? b_q : (z == 1) ? b_k : b_v;
    __nv_bfloat16* Chi = (z == 0) ? g_Qhi : (z == 1) ? g_Khi : g_Vhi;
    __nv_bfloat16* Clo = (z == 0) ? g_Qlo : (z == 1) ? g_Klo : g_Vlo;
    const float scale = (z == 0) ? 0.125f : 1.0f;
    gemm_core(Ahi, Alo, Bhi, Blo, bias, nullptr, Chi, Clo, scale, smem_q);
}

__global__ __launch_bounds__(256, 2) void gemm_o(
    const float* __restrict__ b_o, float* __restrict__ out)
{
    extern __shared__ __align__(128) char smem_o[];
    gemm_core(g_Ahi, g_Alo, g_W4hi + 3 * (size_t)WELEM, g_W4lo + 3 * (size_t)WELEM,
              b_o, out, nullptr, nullptr, 1.0f, smem_o);
}

// ===================== tensor-core flash attention ==========================
// Key tile 32, 3-stage cp.async, 1 sync/iter, Q fragments loaded from GMEM.
// 2 CTAs/SM (regs capped at 128).
#define AKT 32
#define ASTR 72
#define AT_TILE (AKT * ASTR)               // 2304 elems
#define AT_STG_B (4 * AT_TILE * 2)         // 18432 bytes (Kh,Kl,Vh,Vl)
#define ATTN_SMEM (3 * AT_STG_B)           // 55296
#define NKT (SEQ / AKT)                    // 64

__global__ __launch_bounds__(256, 2) void attn_mma()
{
    extern __shared__ __align__(128) __nv_bfloat16 as_[];
    const uint32_t asb = smem_u32_of(as_);

    const int qt = blockIdx.x;
    const int hb = blockIdx.y;
    const int h = hb / BATCH;
    const int b = hb % BATCH;
    const int tid = threadIdx.x;
    const int wid = tid >> 5;
    const int lane = tid & 31;

    const size_t headOff = (size_t)b * SEQ * D_MODEL + (size_t)h * D_K;
    const __nv_bfloat16* Qh = g_Qhi + headOff;
    const __nv_bfloat16* Ql = g_Qlo + headOff;
    const __nv_bfloat16* Kh = g_Khi + headOff;
    const __nv_bfloat16* Kl = g_Klo + headOff;
    const __nv_bfloat16* Vh = g_Vhi + headOff;
    const __nv_bfloat16* Vl = g_Vlo + headOff;

    // K/V stage loader: 4 tiles x 32 rows x 64 elems -> 4 cp16/thread
    const int ldr = tid >> 3;              // 0..31
    const int ldc8 = (tid & 7) * 8;        // 0..56
    auto kvissue = [&](int kt, int stg) {
        const uint32_t sb = asb + (uint32_t)(stg * AT_STG_B);
        const size_t g = (size_t)(kt * AKT + ldr) * D_MODEL + ldc8;
        const uint32_t so = (uint32_t)((ldr * ASTR + ldc8) * 2);
        cp16(sb + 0 * AT_TILE * 2 + so, Kh + g);
        cp16(sb + 1 * AT_TILE * 2 + so, Kl + g);
        cp16(sb + 2 * AT_TILE * 2 + so, Vh + g);
        cp16(sb + 3 * AT_TILE * 2 + so, Vl + g);
    };

    kvissue(0, 0); CP_COMMIT();
    kvissue(1, 1); CP_COMMIT();

    // ---- Q fragments straight from GMEM in mma A-layout ----
    uint32_t qh[4][4], ql[4][4];
    {
        const int fr = lane >> 2;          // 0..7
        const int fc = (lane & 3) * 2;     // 0,2,4,6
        const size_t r0 = (size_t)(qt * 128 + wid * 16 + fr) * D_MODEL;
        const size_t r1 = r0 + 8 * D_MODEL;
        #pragma unroll
        for (int kt = 0; kt < 4; kt++) {
            const int c = kt * 16 + fc;
            qh[kt][0] = *(const uint32_t*)(Qh + r0 + c);
            qh[kt][1] = *(const uint32_t*)(Qh + r1 + c);
            qh[kt][2] = *(const uint32_t*)(Qh + r0 + c + 8);
            qh[kt][3] = *(const uint32_t*)(Qh + r1 + c + 8);
            ql[kt][0] = *(const uint32_t*)(Ql + r0 + c);
            ql[kt][1] = *(const uint32_t*)(Ql + r1 + c);
            ql[kt][2] = *(const uint32_t*)(Ql + r0 + c + 8);
            ql[kt][3] = *(const uint32_t*)(Ql + r1 + c + 8);
        }
    }

    float m0 = -1e30f, m1 = -1e30f, l0 = 0.0f, l1 = 0.0f;
    float o[8][4] = {};

    const uint32_t lof = (uint32_t)(((lane & 15) * ASTR + (lane >> 4) * 8) * 2);
    const uint32_t kB0 = asb + lof;
    const uint32_t kL0 = kB0 + AT_TILE * 2;
    const uint32_t vB0 = kB0 + 2 * AT_TILE * 2;
    const uint32_t vL0 = kB0 + 3 * AT_TILE * 2;

    int sC = 0, sI = 2;
    for (int kt0 = 0; kt0 < NKT; kt0++) {
        CP_WAIT1();
        __syncthreads();
        if (kt0 + 2 < NKT) kvissue(kt0 + 2, sI);
        CP_COMMIT();
        sI = (sI == 2) ? 0 : sI + 1;
        const uint32_t so = (uint32_t)(sC * AT_STG_B);
        sC = (sC == 2) ? 0 : sC + 1;

        // ---- S = Q K^T (16 q-rows x 32 keys), scale pre-folded ----
        float sc[4][4] = {};
        #pragma unroll
        for (int np = 0; np < 2; np++) {
            #pragma unroll
            for (int kt = 0; kt < 4; kt++) {
                const uint32_t off = (uint32_t)(np * 16 * ASTR * 2 + kt * 32) + so;
                uint32_t h0, h1, h2, h3, x0, x1, x2, x3;
                ldmx4(kB0 + off, h0, h1, h2, h3);
                ldmx4(kL0 + off, x0, x1, x2, x3);
                mma16816(sc[2 * np],     qh[kt], h0, h2);
                mma16816(sc[2 * np],     ql[kt], h0, h2);
                mma16816(sc[2 * np],     qh[kt], x0, x2);
                mma16816(sc[2 * np + 1], qh[kt], h1, h3);
                mma16816(sc[2 * np + 1], ql[kt], h1, h3);
                mma16816(sc[2 * np + 1], qh[kt], x1, x3);
            }
        }

        // ---- online softmax ----
        float mx0 = -1e30f, mx1 = -1e30f;
        #pragma unroll
        for (int nt = 0; nt < 4; nt++) {
            mx0 = fmaxf(mx0, fmaxf(sc[nt][0], sc[nt][1]));
            mx1 = fmaxf(mx1, fmaxf(sc[nt][2], sc[nt][3]));
        }
        mx0 = fmaxf(mx0, __shfl_xor_sync(0xffffffffu, mx0, 1));
        mx0 = fmaxf(mx0, __shfl_xor_sync(0xffffffffu, mx0, 2));
        mx1 = fmaxf(mx1, __shfl_xor_sync(0xffffffffu, mx1, 1));
        mx1 = fmaxf(mx1, __shfl_xor_sync(0xffffffffu, mx1, 2));
        const float m0n = fmaxf(m0, mx0), m1n = fmaxf(m1, mx1);
        const float a0 = __expf(m0 - m0n), a1 = __expf(m1 - m1n);
        float rs0 = 0.0f, rs1 = 0.0f;
        #pragma unroll
        for (int nt = 0; nt < 4; nt++) {
            sc[nt][0] = __expf(sc[nt][0] - m0n);
            sc[nt][1] = __expf(sc[nt][1] - m0n);
            sc[nt][2] = __expf(sc[nt][2] - m1n);
            sc[nt][3] = __expf(sc[nt][3] - m1n);
            rs0 += sc[nt][0] + sc[nt][1];
            rs1 += sc[nt][2] + sc[nt][3];
        }
        #pragma unroll
        for (int nt = 0; nt < 8; nt++) {
            o[nt][0] *= a0; o[nt][1] *= a0;
            o[nt][2] *= a1; o[nt][3] *= a1;
        }
        rs0 += __shfl_xor_sync(0xffffffffu, rs0, 1);
        rs0 += __shfl_xor_sync(0xffffffffu, rs0, 2);
        rs1 += __shfl_xor_sync(0xffffffffu, rs1, 1);
        rs1 += __shfl_xor_sync(0xffffffffu, rs1, 2);
        l0 = l0 * a0 + rs0;
        l1 = l1 * a1 + rs1;
        m0 = m0n; m1 = m1n;

        // ---- split P (16x32) into hi/lo fragments, 2 k-tiles ----
        uint32_t ph[2][4], pl[2][4];
        #pragma unroll
        for (int kt = 0; kt < 2; kt++) {
            const float* sa = sc[2 * kt];
            const float* sb2 = sc[2 * kt + 1];
            float hv;
            float la0, la1, la2, la3, lb0, lb1, lb2, lb3;
            hv = __bfloat162float(__float2bfloat16_rn(sa[0])); la0 = sa[0] - hv;
            hv = __bfloat162float(__float2bfloat16_rn(sa[1])); la1 = sa[1] - hv;
            hv = __bfloat162float(__float2bfloat16_rn(sa[2])); la2 = sa[2] - hv;
            hv = __bfloat162float(__float2bfloat16_rn(sa[3])); la3 = sa[3] - hv;
            hv = __bfloat162float(__float2bfloat16_rn(sb2[0])); lb0 = sb2[0] - hv;
            hv = __bfloat162float(__float2bfloat16_rn(sb2[1])); lb1 = sb2[1] - hv;
            hv = __bfloat162float(__float2bfloat16_rn(sb2[2])); lb2 = sb2[2] - hv;
            hv = __bfloat162float(__float2bfloat16_rn(sb2[3])); lb3 = sb2[3] - hv;
            ph[kt][0] = pack_bf16(sa[0], sa[1]);
            ph[kt][1] = pack_bf16(sa[2], sa[3]);
            ph[kt][2] = pack_bf16(sb2[0], sb2[1]);
            ph[kt][3] = pack_bf16(sb2[2], sb2[3]);
            pl[kt][0] = pack_bf16(la0, la1);
            pl[kt][1] = pack_bf16(la2, la3);
            pl[kt][2] = pack_bf16(lb0, lb1);
            pl[kt][3] = pack_bf16(lb2, lb3);
        }

        // ---- O += P @ V (32 keys x 64 dims) ----
        #pragma unroll
        for (int np = 0; np < 4; np++) {
            #pragma unroll
            for (int kt = 0; kt < 2; kt++) {
                const uint32_t off = (uint32_t)((kt * 16 * ASTR + np * 16) * 2) + so;
                uint32_t h0, h1, h2, h3, x0, x1, x2, x3;
                ldmx4t(vB0 + off, h0, h1, h2, h3);
                ldmx4t(vL0 + off, x0, x1, x2, x3);
                mma16816(o[2 * np],     ph[kt], h0, h1);
                mma16816(o[2 * np],     pl[kt], h0, h1);
                mma16816(o[2 * np],     ph[kt], x0, x1);
                mma16816(o[2 * np + 1], ph[kt], h2, h3);
                mma16816(o[2 * np + 1], pl[kt], h2, h3);
                mma16816(o[2 * np + 1], ph[kt], x2, x3);
            }
        }
    }

    // ---- epilogue: normalize, split, write for the O-projection ----
    const float inv0 = 1.0f / l0, inv1 = 1.0f / l1;
    const size_t row0 = (size_t)b * SEQ + qt * 128 + wid * 16 + (lane >> 2);
    const size_t row1 = row0 + 8;
    const int colB = h * D_K + (lane & 3) * 2;
    #pragma unroll
    for (int nt = 0; nt < 8; nt++) {
        const size_t c = colB + nt * 8;
        float v00 = o[nt][0] * inv0, v01 = o[nt][1] * inv0;
        float v10 = o[nt][2] * inv1, v11 = o[nt][3] * inv1;
        __nv_bfloat16 h00 = __float2bfloat16_rn(v00);
        __nv_bfloat16 h01 = __float2bfloat16_rn(v01);
        __nv_bfloat16 h10 = __float2bfloat16_rn(v10);
        __nv_bfloat16 h11 = __float2bfloat16_rn(v11);
        *(__nv_bfloat162*)(g_Ahi + row0 * D_MODEL + c) = __nv_bfloat162(h00, h01);
        *(__nv_bfloat162*)(g_Ahi + row1 * D_MODEL + c) = __nv_bfloat162(h10, h11);
        *(__nv_bfloat162*)(g_Alo + row0 * D_MODEL + c) = __nv_bfloat162(
            __float2bfloat16_rn(v00 - __bfloat162float(h00)),
            __float2bfloat16_rn(v01 - __bfloat162float(h01)));
        *(__nv_bfloat162*)(g_Alo + row1 * D_MODEL + c) = __nv_bfloat162(
            __float2bfloat16_rn(v10 - __bfloat162float(h10)),
            __float2bfloat16_rn(v11 - __bfloat162float(h11)));
    }
}

// ===================== launch ==============================================
extern "C" void kernel_launch(void* const* d_in, const int* in_sizes, int n_in,
                              void* d_out, int out_size)
{
    const float* q   = (const float*)d_in[0];
    const float* k   = (const float*)d_in[1];
    const float* v   = (const float*)d_in[2];
    const float* w_q = (const float*)d_in[3];
    const float* b_q = (const float*)d_in[4];
    const float* w_k = (const float*)d_in[5];
    const float* b_k = (const float*)d_in[6];
    const float* w_v = (const float*)d_in[7];
    const float* b_v = (const float*)d_in[8];
    const float* w_o = (const float*)d_in[9];
    const float* b_o = (const float*)d_in[10];
    float* out = (float*)d_out;

    cudaFuncSetAttribute(gemm_qkv, cudaFuncAttributeMaxDynamicSharedMemorySize, G_SMEM);
    cudaFuncSetAttribute(gemm_o,   cudaFuncAttributeMaxDynamicSharedMemorySize, G_SMEM);
    cudaFuncSetAttribute(attn_mma, cudaFuncAttributeMaxDynamicSharedMemorySize, ATTN_SMEM);

    const int n4 = XELEM / 4;

    wsplit_all<<<dim3(32, 32, 4), dim3(32, 8)>>>(w_q, w_k, w_v, w_o);
    split_all<<<dim3(n4 / 256, 3), 256>>>(q, k, v);

    gemm_qkv<<<dim3(D_MODEL / GBN, MROWS / GBM, 3), 256, G_SMEM>>>(b_q, b_k, b_v);

    attn_mma<<<dim3(SEQ / 128, N_HEAD * BATCH), 256, ATTN_SMEM>>>();

    gemm_o<<<dim3(D_MODEL / GBN, MROWS / GBM), 256, G_SMEM>>>(b_o, out);
}